// round 1
// baseline (speedup 1.0000x reference)
#include <cuda_runtime.h>
#include <math.h>

#define B_ 4
#define T_ 1024
#define C_ 1024
#define H_ 16
#define HD 64

// ---------------- scratch (static device globals; no allocation) -------------
__device__ __align__(16) float g_qkv[(size_t)4096 * 3072];
__device__ __align__(16) float g_q[(size_t)4096 * 1024];
__device__ __align__(16) float g_k[(size_t)4096 * 1024];
__device__ __align__(16) float g_v[(size_t)4096 * 1024];
__device__ float g_q0[(size_t)B_ * H_ * T_];
__device__ float g_k0[(size_t)B_ * H_ * T_];
__device__ __align__(16) float g_o[(size_t)4096 * 1024];

// ---------------- SGEMM: C[m][n] = sum_k A[m][k] * B[n][k] -------------------
// 128x128 block tile, BK=16, 256 threads, 8x8 per-thread microtile.
// Requires M%128==0, N%128==0, K%16==0 (true for all calls here).
__global__ __launch_bounds__(256) void sgemm_abt(
    const float* __restrict__ A, const float* __restrict__ Bm,
    float* __restrict__ Cm, int M, int N, int K)
{
    __shared__ float As[16][128];
    __shared__ float Bs[16][128];

    const int tid = threadIdx.x;
    const int bm = blockIdx.y * 128;
    const int bn = blockIdx.x * 128;
    const int tx = tid & 15;     // 0..15 -> n
    const int ty = tid >> 4;     // 0..15 -> m

    float acc[8][8] = {};

    for (int k0 = 0; k0 < K; k0 += 16) {
#pragma unroll
        for (int i = 0; i < 2; i++) {
            int f = tid + i * 256;        // 0..511 float4 slots
            int row = f >> 2;             // 0..127
            int kc = (f & 3) * 4;         // 0,4,8,12
            float4 a = *(const float4*)(A + (size_t)(bm + row) * K + k0 + kc);
            As[kc + 0][row] = a.x; As[kc + 1][row] = a.y;
            As[kc + 2][row] = a.z; As[kc + 3][row] = a.w;
            float4 b = *(const float4*)(Bm + (size_t)(bn + row) * K + k0 + kc);
            Bs[kc + 0][row] = b.x; Bs[kc + 1][row] = b.y;
            Bs[kc + 2][row] = b.z; Bs[kc + 3][row] = b.w;
        }
        __syncthreads();
#pragma unroll
        for (int kk = 0; kk < 16; kk++) {
            float ar[8], br[8];
#pragma unroll
            for (int i = 0; i < 8; i++) ar[i] = As[kk][ty * 8 + i];
#pragma unroll
            for (int j = 0; j < 8; j++) br[j] = Bs[kk][tx * 8 + j];
#pragma unroll
            for (int i = 0; i < 8; i++)
#pragma unroll
                for (int j = 0; j < 8; j++)
                    acc[i][j] = fmaf(ar[i], br[j], acc[i][j]);
        }
        __syncthreads();
    }

#pragma unroll
    for (int i = 0; i < 8; i++) {
        int m = bm + ty * 8 + i;
#pragma unroll
        for (int j = 0; j < 8; j += 4) {
            float4 o4 = make_float4(acc[i][j], acc[i][j + 1], acc[i][j + 2], acc[i][j + 3]);
            *(float4*)(Cm + (size_t)m * N + bn + tx * 8 + j) = o4;
        }
    }
}

// ---------------- RoPE + split to [B,H,T,hd] + q0/k0 norms -------------------
// One warp (32 threads) per (b,t,h). Thread j handles rotation pair (j, j+32).
__global__ void rope_split(const float* __restrict__ qkv, const float* __restrict__ hyp)
{
    int bi = blockIdx.x;                 // b*T*H + t*H + h
    int h = bi % H_;
    int t = (bi / H_) % T_;
    int b = bi / (H_ * T_);
    int j = threadIdx.x;                 // 0..31

    const float* src = qkv + (size_t)(b * T_ + t) * (3 * C_) + h * HD;
    float kc = hyp[h];

    float inv = powf(10000.0f, -(float)(2 * j) / 64.0f);
    float fr = (float)t * inv;
    float cs = cosf(fr);
    float sn = sinf(fr);

    size_t dst = ((size_t)(b * H_ + h) * T_ + t) * HD;

    float q1 = src[j], q2 = src[j + 32];
    float qo1 = q1 * cs + q2 * sn;
    float qo2 = -q1 * sn + q2 * cs;
    g_q[dst + j] = qo1;
    g_q[dst + j + 32] = qo2;

    float k1 = src[C_ + j], k2 = src[C_ + j + 32];
    float ko1 = k1 * cs + k2 * sn;
    float ko2 = -k1 * sn + k2 * cs;
    g_k[dst + j] = ko1;
    g_k[dst + j + 32] = ko2;

    g_v[dst + j] = src[2 * C_ + j];
    g_v[dst + j + 32] = src[2 * C_ + j + 32];

    float sq = qo1 * qo1 + qo2 * qo2;
    float sk = ko1 * ko1 + ko2 * ko2;
#pragma unroll
    for (int off = 16; off; off >>= 1) {
        sq += __shfl_xor_sync(0xffffffffu, sq, off);
        sk += __shfl_xor_sync(0xffffffffu, sk, off);
    }
    if (j == 0) {
        size_t r = (size_t)(b * H_ + h) * T_ + t;
        g_q0[r] = sqrtf(kc + sq);
        g_k0[r] = sqrtf(kc + sk);
    }
}

// ---------------- Attention: one block per query row --------------------------
__global__ __launch_bounds__(128) void attn_kernel(const float* __restrict__ hyp)
{
    __shared__ float sq[64];
    __shared__ float sc[1024];
    __shared__ float red[4];
    __shared__ float accb[128];

    const int l = blockIdx.x;
    const int h = blockIdx.y;
    const int b = blockIdx.z;
    const int tid = threadIdx.x;

    const size_t bh = (size_t)(b * H_ + h);
    const float* Kp = g_k + bh * T_ * HD;
    const float* Vp = g_v + bh * T_ * HD;
    const float* Qp = g_q + (bh * T_ + l) * HD;

    if (tid < 64) sq[tid] = Qp[tid];
    const float kc = hyp[h];
    const float inv_k = 1.0f / kc;
    const float sqk = sqrtf(kc);
    const float q0 = g_q0[bh * T_ + l];
    __syncthreads();

    // phase 1: scores + local max
    float lmax = -1e30f;
    for (int s = tid; s <= l; s += 128) {
        const float4* kr = (const float4*)(Kp + (size_t)s * HD);
        float dot = 0.0f;
#pragma unroll
        for (int i = 0; i < 16; i++) {
            float4 kv = kr[i];
            dot = fmaf(sq[4 * i + 0], kv.x, dot);
            dot = fmaf(sq[4 * i + 1], kv.y, dot);
            dot = fmaf(sq[4 * i + 2], kv.z, dot);
            dot = fmaf(sq[4 * i + 3], kv.w, dot);
        }
        float inner = dot - q0 * g_k0[bh * T_ + s];
        float arg = fmaxf(-inner * inv_k, 1.0f + 1e-6f);
        float dis = sqk * acoshf(arg);
        float w = 1.0f / (1e-6f + dis);
        sc[s] = w;
        lmax = fmaxf(lmax, w);
    }
#pragma unroll
    for (int off = 16; off; off >>= 1)
        lmax = fmaxf(lmax, __shfl_xor_sync(0xffffffffu, lmax, off));
    if ((tid & 31) == 0) red[tid >> 5] = lmax;
    __syncthreads();
    const float m = fmaxf(fmaxf(red[0], red[1]), fmaxf(red[2], red[3]));
    __syncthreads();   // everyone done reading red before reuse

    // phase 2: exp + sum (each thread touches only its own sc entries)
    float lsum = 0.0f;
    for (int s = tid; s <= l; s += 128) {
        float p = expf(sc[s] - m);
        sc[s] = p;
        lsum += p;
    }
#pragma unroll
    for (int off = 16; off; off >>= 1)
        lsum += __shfl_xor_sync(0xffffffffu, lsum, off);
    if ((tid & 31) == 0) red[tid >> 5] = lsum;
    __syncthreads();
    const float inv_sum = 1.0f / (red[0] + red[1] + red[2] + red[3]);

    // phase 3: PV. 2-way split over s, 64 output dims, coalesced V reads.
    const int d = tid & 63;
    const int part = tid >> 6;
    float acc = 0.0f;
    for (int s = part; s <= l; s += 2)
        acc = fmaf(sc[s], Vp[(size_t)s * HD + d], acc);
    accb[tid] = acc;
    __syncthreads();
    if (tid < 64) {
        float o = (accb[tid] + accb[tid + 64]) * inv_sum;
        g_o[((size_t)(b * T_) + l) * C_ + h * HD + tid] = o;
    }
}

// ---------------- launch ------------------------------------------------------
extern "C" void kernel_launch(void* const* d_in, const int* in_sizes, int n_in,
                              void* d_out, int out_size)
{
    const float* x    = (const float*)d_in[0];
    const float* Wqkv = (const float*)d_in[1];
    const float* Wout = (const float*)d_in[2];
    const float* hyp  = (const float*)d_in[3];
    float* out = (float*)d_out;

    static float* p_qkv = nullptr;
    static float* p_o = nullptr;
    if (!p_qkv) {
        cudaGetSymbolAddress((void**)&p_qkv, g_qkv);
        cudaGetSymbolAddress((void**)&p_o, g_o);
    }

    // 1) qkv = x @ W_qkv^T : (4096 x 1024) @ (1024 x 3072)
    sgemm_abt<<<dim3(3072 / 128, 4096 / 128), 256>>>(x, Wqkv, p_qkv, 4096, 3072, 1024);

    // 2) RoPE + split + norms
    rope_split<<<B_ * T_ * H_, 32>>>(p_qkv, hyp);

    // 3) attention
    attn_kernel<<<dim3(T_, H_, B_), 128>>>(hyp);

    // 4) out = o @ W_out^T : (4096 x 1024) @ (1024 x 1024)
    sgemm_abt<<<dim3(1024 / 128, 4096 / 128), 256>>>(p_o, Wout, out, 4096, 1024, 1024);
}

// round 2
// speedup vs baseline: 2.4640x; 2.4640x over previous
#include <cuda_runtime.h>
#include <math.h>

#define B_ 4
#define T_ 1024
#define C_ 1024
#define H_ 16
#define HD 64

// ---------------- scratch (static device globals; no allocation) -------------
__device__ __align__(16) float g_qkv[(size_t)4096 * 3072];
__device__ __align__(16) float g_q[(size_t)4096 * 1024];
__device__ __align__(16) float g_k[(size_t)4096 * 1024];
__device__ __align__(16) float g_v[(size_t)4096 * 1024];
__device__ float g_q0[(size_t)B_ * H_ * T_];
__device__ float g_k0[(size_t)B_ * H_ * T_];
__device__ __align__(16) float g_o[(size_t)4096 * 1024];

// ---------------- SGEMM: C[m][n] = sum_k A[m][k] * B[n][k] -------------------
__global__ __launch_bounds__(256) void sgemm_abt(
    const float* __restrict__ A, const float* __restrict__ Bm,
    float* __restrict__ Cm, int M, int N, int K)
{
    __shared__ float As[16][128];
    __shared__ float Bs[16][128];

    const int tid = threadIdx.x;
    const int bm = blockIdx.y * 128;
    const int bn = blockIdx.x * 128;
    const int tx = tid & 15;
    const int ty = tid >> 4;

    float acc[8][8] = {};

    for (int k0 = 0; k0 < K; k0 += 16) {
#pragma unroll
        for (int i = 0; i < 2; i++) {
            int f = tid + i * 256;
            int row = f >> 2;
            int kc = (f & 3) * 4;
            float4 a = *(const float4*)(A + (size_t)(bm + row) * K + k0 + kc);
            As[kc + 0][row] = a.x; As[kc + 1][row] = a.y;
            As[kc + 2][row] = a.z; As[kc + 3][row] = a.w;
            float4 b = *(const float4*)(Bm + (size_t)(bn + row) * K + k0 + kc);
            Bs[kc + 0][row] = b.x; Bs[kc + 1][row] = b.y;
            Bs[kc + 2][row] = b.z; Bs[kc + 3][row] = b.w;
        }
        __syncthreads();
#pragma unroll
        for (int kk = 0; kk < 16; kk++) {
            float ar[8], br[8];
#pragma unroll
            for (int i = 0; i < 8; i++) ar[i] = As[kk][ty * 8 + i];
#pragma unroll
            for (int j = 0; j < 8; j++) br[j] = Bs[kk][tx * 8 + j];
#pragma unroll
            for (int i = 0; i < 8; i++)
#pragma unroll
                for (int j = 0; j < 8; j++)
                    acc[i][j] = fmaf(ar[i], br[j], acc[i][j]);
        }
        __syncthreads();
    }

#pragma unroll
    for (int i = 0; i < 8; i++) {
        int m = bm + ty * 8 + i;
#pragma unroll
        for (int j = 0; j < 8; j += 4) {
            float4 o4 = make_float4(acc[i][j], acc[i][j + 1], acc[i][j + 2], acc[i][j + 3]);
            *(float4*)(Cm + (size_t)m * N + bn + tx * 8 + j) = o4;
        }
    }
}

// ---------------- RoPE + split to [B,H,T,hd] + q0/k0 norms -------------------
__global__ void rope_split(const float* __restrict__ qkv, const float* __restrict__ hyp)
{
    int bi = blockIdx.x;
    int h = bi % H_;
    int t = (bi / H_) % T_;
    int b = bi / (H_ * T_);
    int j = threadIdx.x;

    const float* src = qkv + (size_t)(b * T_ + t) * (3 * C_) + h * HD;
    float kc = hyp[h];

    float inv = powf(10000.0f, -(float)(2 * j) / 64.0f);
    float fr = (float)t * inv;
    float cs = cosf(fr);
    float sn = sinf(fr);

    size_t dst = ((size_t)(b * H_ + h) * T_ + t) * HD;

    float q1 = src[j], q2 = src[j + 32];
    float qo1 = q1 * cs + q2 * sn;
    float qo2 = -q1 * sn + q2 * cs;
    g_q[dst + j] = qo1;
    g_q[dst + j + 32] = qo2;

    float k1 = src[C_ + j], k2 = src[C_ + j + 32];
    float ko1 = k1 * cs + k2 * sn;
    float ko2 = -k1 * sn + k2 * cs;
    g_k[dst + j] = ko1;
    g_k[dst + j + 32] = ko2;

    g_v[dst + j] = src[2 * C_ + j];
    g_v[dst + j + 32] = src[2 * C_ + j + 32];

    float sq = qo1 * qo1 + qo2 * qo2;
    float sk = ko1 * ko1 + ko2 * ko2;
#pragma unroll
    for (int off = 16; off; off >>= 1) {
        sq += __shfl_xor_sync(0xffffffffu, sq, off);
        sk += __shfl_xor_sync(0xffffffffu, sk, off);
    }
    if (j == 0) {
        size_t r = (size_t)(b * H_ + h) * T_ + t;
        g_q0[r] = sqrtf(kc + sq);
        g_k0[r] = sqrtf(kc + sk);
    }
}

// ---------------- Flash attention: 64x64 tiles, online softmax ---------------
// 256 threads = 16x16; each thread owns a 4x4 microtile (rows=ty*4.., cols=tx*4..).
__global__ __launch_bounds__(256) void attn_flash(const float* __restrict__ hyp)
{
    extern __shared__ float sm[];
    float* sQ  = sm;            // [kk][row]   (64x64, kk-major)
    float* sK  = sQ + 4096;     // [kk][col]
    float* sV  = sK + 4096;     // [s][d]      (row-major)
    float* sP  = sV + 4096;     // [row][s]
    float* sq0 = sP + 4096;     // [64]
    float* sk0 = sq0 + 64;      // [64]

    const int qt = blockIdx.x, h = blockIdx.y, b = blockIdx.z;
    const int tid = threadIdx.x;
    const int tx = tid & 15, ty = tid >> 4;
    const int row0 = ty * 4, col0 = tx * 4;
    const size_t bh = (size_t)b * H_ + h;
    const float* Qg = g_q + (bh * T_ + (size_t)qt * 64) * HD;
    const float* Kg = g_k + bh * T_ * HD;
    const float* Vg = g_v + bh * T_ * HD;

    const float kc   = hyp[h];
    const float invk = 1.0f / kc;
    const float sqk  = sqrtf(kc);

    // load Q tile transposed (kk-major)
#pragma unroll
    for (int i = 0; i < 4; i++) {
        int f  = tid + i * 256;          // 0..1023 float4 slots
        int r  = f & 63;
        int k4 = (f >> 6) * 4;
        float4 q4 = *(const float4*)(Qg + r * 64 + k4);
        sQ[(k4 + 0) * 64 + r] = q4.x;
        sQ[(k4 + 1) * 64 + r] = q4.y;
        sQ[(k4 + 2) * 64 + r] = q4.z;
        sQ[(k4 + 3) * 64 + r] = q4.w;
    }
    if (tid < 64) sq0[tid] = g_q0[bh * T_ + qt * 64 + tid];

    float O[4][4] = {};
    float mrow[4] = {-1e30f, -1e30f, -1e30f, -1e30f};
    float lrow[4] = {};

    for (int st = 0; st <= qt; st++) {
        const float* Kt = Kg + (size_t)st * 64 * 64;
        const float* Vt = Vg + (size_t)st * 64 * 64;
#pragma unroll
        for (int i = 0; i < 4; i++) {
            int f  = tid + i * 256;
            int r  = f & 63;
            int k4 = (f >> 6) * 4;
            float4 k4v = *(const float4*)(Kt + r * 64 + k4);
            sK[(k4 + 0) * 64 + r] = k4v.x;
            sK[(k4 + 1) * 64 + r] = k4v.y;
            sK[(k4 + 2) * 64 + r] = k4v.z;
            sK[(k4 + 3) * 64 + r] = k4v.w;
            int s  = f >> 4;
            int d4 = (f & 15) * 4;
            *(float4*)(sV + s * 64 + d4) = *(const float4*)(Vt + s * 64 + d4);
        }
        if (tid < 64) sk0[tid] = g_k0[bh * T_ + st * 64 + tid];
        __syncthreads();

        // S = Q K^T (4x4 microtile)
        float S[4][4] = {};
#pragma unroll 8
        for (int kk = 0; kk < 64; kk++) {
            float4 a  = *(const float4*)(sQ + kk * 64 + row0);
            float4 bb = *(const float4*)(sK + kk * 64 + col0);
            float ar[4] = {a.x, a.y, a.z, a.w};
            float br[4] = {bb.x, bb.y, bb.z, bb.w};
#pragma unroll
            for (int i = 0; i < 4; i++)
#pragma unroll
                for (int j = 0; j < 4; j++)
                    S[i][j] = fmaf(ar[i], br[j], S[i][j]);
        }

        // hyperbolic score transform + causal mask
        float q0r[4], k0c[4];
#pragma unroll
        for (int i = 0; i < 4; i++) q0r[i] = sq0[row0 + i];
#pragma unroll
        for (int j = 0; j < 4; j++) k0c[j] = sk0[col0 + j];
        const bool diag = (st == qt);
#pragma unroll
        for (int i = 0; i < 4; i++) {
#pragma unroll
            for (int j = 0; j < 4; j++) {
                float inner = S[i][j] - q0r[i] * k0c[j];
                float arg   = fmaxf(-inner * invk, 1.0f + 1e-6f);
                float tm    = arg - 1.0f;
                float dis   = sqk * __logf(arg + sqrtf(tm * (arg + 1.0f)));
                float w     = 1.0f / (1e-6f + dis);
                if (diag && (col0 + j) > (row0 + i)) w = -1e30f;
                S[i][j] = w;
            }
        }

        // online softmax update (row reductions over the 16 tx lanes)
#pragma unroll
        for (int i = 0; i < 4; i++) {
            float rmax = fmaxf(fmaxf(S[i][0], S[i][1]), fmaxf(S[i][2], S[i][3]));
#pragma unroll
            for (int off = 1; off < 16; off <<= 1)
                rmax = fmaxf(rmax, __shfl_xor_sync(0xffffffffu, rmax, off));
            float nm = fmaxf(mrow[i], rmax);
            float alpha = __expf(mrow[i] - nm);
            mrow[i] = nm;
            float rsum = 0.0f;
#pragma unroll
            for (int j = 0; j < 4; j++) {
                float p = __expf(S[i][j] - nm);
                S[i][j] = p;
                rsum += p;
            }
#pragma unroll
            for (int off = 1; off < 16; off <<= 1)
                rsum += __shfl_xor_sync(0xffffffffu, rsum, off);
            lrow[i] = lrow[i] * alpha + rsum;
#pragma unroll
            for (int j = 0; j < 4; j++) O[i][j] *= alpha;
        }

        // stage P, then O += P V
#pragma unroll
        for (int i = 0; i < 4; i++)
            *(float4*)(sP + (row0 + i) * 64 + col0) =
                make_float4(S[i][0], S[i][1], S[i][2], S[i][3]);
        __syncthreads();

#pragma unroll 8
        for (int s = 0; s < 64; s++) {
            float4 v = *(const float4*)(sV + s * 64 + col0);
            float vr[4] = {v.x, v.y, v.z, v.w};
            float pr[4];
#pragma unroll
            for (int i = 0; i < 4; i++) pr[i] = sP[(row0 + i) * 64 + s];
#pragma unroll
            for (int i = 0; i < 4; i++)
#pragma unroll
                for (int j = 0; j < 4; j++)
                    O[i][j] = fmaf(pr[i], vr[j], O[i][j]);
        }
        __syncthreads();
    }

    // epilogue: normalize and scatter to [B,T,C] layout
#pragma unroll
    for (int i = 0; i < 4; i++) {
        float inv = 1.0f / lrow[i];
        int r = qt * 64 + row0 + i;
        float4 o = make_float4(O[i][0] * inv, O[i][1] * inv,
                               O[i][2] * inv, O[i][3] * inv);
        *(float4*)(g_o + ((size_t)b * T_ + r) * C_ + h * 64 + col0) = o;
    }
}

// ---------------- launch ------------------------------------------------------
extern "C" void kernel_launch(void* const* d_in, const int* in_sizes, int n_in,
                              void* d_out, int out_size)
{
    const float* x    = (const float*)d_in[0];
    const float* Wqkv = (const float*)d_in[1];
    const float* Wout = (const float*)d_in[2];
    const float* hyp  = (const float*)d_in[3];
    float* out = (float*)d_out;

    static float* p_qkv = nullptr;
    static float* p_o = nullptr;
    if (!p_qkv) {
        cudaGetSymbolAddress((void**)&p_qkv, g_qkv);
        cudaGetSymbolAddress((void**)&p_o, g_o);
        cudaFuncSetAttribute(attn_flash,
                             cudaFuncAttributeMaxDynamicSharedMemorySize,
                             (4 * 4096 + 128) * sizeof(float));
    }

    // 1) qkv = x @ W_qkv^T : (4096 x 1024) @ (1024 x 3072)
    sgemm_abt<<<dim3(3072 / 128, 4096 / 128), 256>>>(x, Wqkv, p_qkv, 4096, 3072, 1024);

    // 2) RoPE + split + norms
    rope_split<<<B_ * T_ * H_, 32>>>(p_qkv, hyp);

    // 3) flash attention (64x64 tiles)
    attn_flash<<<dim3(T_ / 64, H_, B_), 256, (4 * 4096 + 128) * sizeof(float)>>>(hyp);

    // 4) out = o @ W_out^T : (4096 x 1024) @ (1024 x 1024)
    sgemm_abt<<<dim3(1024 / 128, 4096 / 128), 256>>>(p_o, Wout, out, 4096, 1024, 1024);
}

// round 4
// speedup vs baseline: 4.0297x; 1.6354x over previous
#include <cuda_runtime.h>
#include <cuda_bf16.h>
#include <math.h>
#include <stdint.h>

#define B_ 4
#define T_ 1024
#define C_ 1024
#define H_ 16
#define HD 64

// ---------------- scratch (static device globals; no allocation) -------------
__device__ __align__(16) float g_qkv[(size_t)4096 * 3072];
__device__ __align__(16) float g_q[(size_t)4096 * 1024];
__device__ __align__(16) float g_k[(size_t)4096 * 1024];
__device__ __align__(16) float g_v[(size_t)4096 * 1024];
__device__ float g_q0[(size_t)B_ * H_ * T_];
__device__ float g_k0[(size_t)B_ * H_ * T_];
__device__ __align__(16) float g_o[(size_t)4096 * 1024];

// ---------------- helpers ------------------------------------------------------
__device__ __forceinline__ uint32_t smem_u32(const void* p) {
    uint32_t a;
    asm("{ .reg .u64 t; cvta.to.shared.u64 t, %1; cvt.u32.u64 %0, t; }" : "=r"(a) : "l"(p));
    return a;
}

__device__ __forceinline__ void ldm_x4(uint32_t& r0, uint32_t& r1, uint32_t& r2, uint32_t& r3,
                                       uint32_t addr) {
    asm volatile("ldmatrix.sync.aligned.m8n8.x4.shared.b16 {%0,%1,%2,%3}, [%4];"
                 : "=r"(r0), "=r"(r1), "=r"(r2), "=r"(r3) : "r"(addr));
}
__device__ __forceinline__ void ldm_x2(uint32_t& r0, uint32_t& r1, uint32_t addr) {
    asm volatile("ldmatrix.sync.aligned.m8n8.x2.shared.b16 {%0,%1}, [%2];"
                 : "=r"(r0), "=r"(r1) : "r"(addr));
}
__device__ __forceinline__ void mma16816(float* d, const uint32_t* a, const uint32_t* b) {
    asm volatile("mma.sync.aligned.m16n8k16.row.col.f32.bf16.bf16.f32 "
                 "{%0,%1,%2,%3}, {%4,%5,%6,%7}, {%8,%9}, {%0,%1,%2,%3};"
                 : "+f"(d[0]), "+f"(d[1]), "+f"(d[2]), "+f"(d[3])
                 : "r"(a[0]), "r"(a[1]), "r"(a[2]), "r"(a[3]), "r"(b[0]), "r"(b[1]));
}

// pack two floats into bf16x2 hi, and return residual bf16x2 lo
__device__ __forceinline__ void split2(float x, float y, uint32_t& hi, uint32_t& lo) {
    __nv_bfloat16 hx = __float2bfloat16(x), hy = __float2bfloat16(y);
    __nv_bfloat162 h(hx, hy);
    __nv_bfloat162 l(__float2bfloat16(x - __bfloat162float(hx)),
                     __float2bfloat16(y - __bfloat162float(hy)));
    hi = *(uint32_t*)&h;
    lo = *(uint32_t*)&l;
}

// ---------------- tensor-core GEMM: C[m][n] = sum_k A[m][k]*B[n][k] ----------
// fp32 in/out, bf16 hi/lo split, mma.sync m16n8k16, 128x128x32 tiles, 256 thr.
// smem stage: sAh(10240) sAl(10240) sBh(10240) sBl(10240) = 40960 B, x2 stages.
#define GST 40960
#define ROWB 80   // padded row stride in bytes (32 bf16 data + 8 pad)

__global__ __launch_bounds__(256) void gemm_mma(
    const float* __restrict__ A, const float* __restrict__ B,
    float* __restrict__ C, int M, int N, int K)
{
    extern __shared__ __align__(128) char smem[];
    const uint32_t sb = smem_u32(smem);
    const int tid = threadIdx.x;
    const int lane = tid & 31, warp = tid >> 5;
    const int wm = warp >> 2, wn = warp & 3;            // warp tile: 64(M) x 32(N)
    const int bm = blockIdx.y * 128, bn = blockIdx.x * 128;
    const int NC = K / 32;

    const int lrow = tid >> 3;          // 0..31 (+32 per j)
    const int lslot = tid & 7;          // float4 slot within 32-float row

    float4 pA[4], pB[4];
#pragma unroll
    for (int j = 0; j < 4; j++) {
        pA[j] = *(const float4*)(A + (size_t)(bm + lrow + j * 32) * K + lslot * 4);
        pB[j] = *(const float4*)(B + (size_t)(bn + lrow + j * 32) * K + lslot * 4);
    }

    // STS helper (stage st): row r, slot -> bytes r*80 + slot*8
    auto sts_all = [&](int st) {
        uint32_t base = sb + st * GST;
#pragma unroll
        for (int j = 0; j < 4; j++) {
            int r = lrow + j * 32;
            uint32_t off = (uint32_t)(r * ROWB + lslot * 8);
            uint32_t h0, l0, h1, l1;
            split2(pA[j].x, pA[j].y, h0, l0);
            split2(pA[j].z, pA[j].w, h1, l1);
            *(uint2*)(smem + (st * GST) + r * ROWB + lslot * 8) = make_uint2(h0, h1);
            *(uint2*)(smem + (st * GST) + 10240 + r * ROWB + lslot * 8) = make_uint2(l0, l1);
            split2(pB[j].x, pB[j].y, h0, l0);
            split2(pB[j].z, pB[j].w, h1, l1);
            *(uint2*)(smem + (st * GST) + 20480 + r * ROWB + lslot * 8) = make_uint2(h0, h1);
            *(uint2*)(smem + (st * GST) + 30720 + r * ROWB + lslot * 8) = make_uint2(l0, l1);
            (void)base; (void)off;
        }
    };

    sts_all(0);
    __syncthreads();

    float acc[16][4] = {};

    // ldmatrix address pieces (constant per thread)
    const uint32_t aoff = (uint32_t)((wm * 64 + (lane & 15)) * ROWB + (lane >> 4) * 16);
    const uint32_t boff = (uint32_t)((wn * 32 + (lane & 7)) * ROWB + ((lane >> 3) & 1) * 16);

    for (int i = 0; i < NC; i++) {
        const int s = i & 1;
        if (i + 1 < NC) {
            const int k0 = (i + 1) * 32;
#pragma unroll
            for (int j = 0; j < 4; j++) {
                pA[j] = *(const float4*)(A + (size_t)(bm + lrow + j * 32) * K + k0 + lslot * 4);
                pB[j] = *(const float4*)(B + (size_t)(bn + lrow + j * 32) * K + k0 + lslot * 4);
            }
        }

        const uint32_t sAh = sb + s * GST;
        const uint32_t sAl = sAh + 10240;
        const uint32_t sBh = sAh + 20480;
        const uint32_t sBl = sAh + 30720;

#pragma unroll
        for (int kk = 0; kk < 2; kk++) {
            uint32_t ah[4][4], al[4][4], bh[4][2], bl[4][2];
#pragma unroll
            for (int am = 0; am < 4; am++) {
                uint32_t ad = aoff + am * 16 * ROWB + kk * 32;
                ldm_x4(ah[am][0], ah[am][1], ah[am][2], ah[am][3], sAh + ad);
                ldm_x4(al[am][0], al[am][1], al[am][2], al[am][3], sAl + ad);
            }
#pragma unroll
            for (int bt = 0; bt < 4; bt++) {
                uint32_t bd = boff + bt * 8 * ROWB + kk * 32;
                ldm_x2(bh[bt][0], bh[bt][1], sBh + bd);
                ldm_x2(bl[bt][0], bl[bt][1], sBl + bd);
            }
#pragma unroll
            for (int am = 0; am < 4; am++)
#pragma unroll
                for (int bt = 0; bt < 4; bt++) {
                    mma16816(acc[am * 4 + bt], ah[am], bh[bt]);
                    mma16816(acc[am * 4 + bt], ah[am], bl[bt]);
                    mma16816(acc[am * 4 + bt], al[am], bh[bt]);
                }
        }

        if (i + 1 < NC) {
            sts_all(s ^ 1);
        }
        __syncthreads();
    }

    // epilogue: direct fp32 stores (float2 per fragment half-row)
    const int er = bm + wm * 64 + (lane >> 2);
    const int ec = bn + wn * 32 + (lane & 3) * 2;
#pragma unroll
    for (int am = 0; am < 4; am++)
#pragma unroll
        for (int bt = 0; bt < 4; bt++) {
            float* d = acc[am * 4 + bt];
            int r = er + am * 16;
            int c = ec + bt * 8;
            *(float2*)(C + (size_t)r * N + c) = make_float2(d[0], d[1]);
            *(float2*)(C + (size_t)(r + 8) * N + c) = make_float2(d[2], d[3]);
        }
}

// ---------------- RoPE + split to [B,H,T,hd] + q0/k0 norms -------------------
__global__ void rope_split(const float* __restrict__ qkv, const float* __restrict__ hyp)
{
    int bi = blockIdx.x;
    int h = bi % H_;
    int t = (bi / H_) % T_;
    int b = bi / (H_ * T_);
    int j = threadIdx.x;

    const float* src = qkv + (size_t)(b * T_ + t) * (3 * C_) + h * HD;
    float kc = hyp[h];

    float inv = powf(10000.0f, -(float)(2 * j) / 64.0f);
    float fr = (float)t * inv;
    float cs = cosf(fr);
    float sn = sinf(fr);

    size_t dst = ((size_t)(b * H_ + h) * T_ + t) * HD;

    float q1 = src[j], q2 = src[j + 32];
    float qo1 = q1 * cs + q2 * sn;
    float qo2 = -q1 * sn + q2 * cs;
    g_q[dst + j] = qo1;
    g_q[dst + j + 32] = qo2;

    float k1 = src[C_ + j], k2 = src[C_ + j + 32];
    float ko1 = k1 * cs + k2 * sn;
    float ko2 = -k1 * sn + k2 * cs;
    g_k[dst + j] = ko1;
    g_k[dst + j + 32] = ko2;

    g_v[dst + j] = src[2 * C_ + j];
    g_v[dst + j + 32] = src[2 * C_ + j + 32];

    float sq = qo1 * qo1 + qo2 * qo2;
    float sk = ko1 * ko1 + ko2 * ko2;
#pragma unroll
    for (int off = 16; off; off >>= 1) {
        sq += __shfl_xor_sync(0xffffffffu, sq, off);
        sk += __shfl_xor_sync(0xffffffffu, sk, off);
    }
    if (j == 0) {
        size_t r = (size_t)(b * H_ + h) * T_ + t;
        g_q0[r] = sqrtf(kc + sq);
        g_k0[r] = sqrtf(kc + sk);
    }
}

// ---------------- Flash attention: 64x64 tiles, online softmax ---------------
__global__ __launch_bounds__(256) void attn_flash(const float* __restrict__ hyp)
{
    extern __shared__ float sm[];
    float* sQ  = sm;
    float* sK  = sQ + 4096;
    float* sV  = sK + 4096;
    float* sP  = sV + 4096;
    float* sq0 = sP + 4096;
    float* sk0 = sq0 + 64;

    const int qt = blockIdx.x, h = blockIdx.y, b = blockIdx.z;
    const int tid = threadIdx.x;
    const int tx = tid & 15, ty = tid >> 4;
    const int row0 = ty * 4, col0 = tx * 4;
    const size_t bh = (size_t)b * H_ + h;
    const float* Qg = g_q + (bh * T_ + (size_t)qt * 64) * HD;
    const float* Kg = g_k + bh * T_ * HD;
    const float* Vg = g_v + bh * T_ * HD;

    const float kc   = hyp[h];
    const float invk = 1.0f / kc;
    const float sqk  = sqrtf(kc);

#pragma unroll
    for (int i = 0; i < 4; i++) {
        int f  = tid + i * 256;
        int r  = f & 63;
        int k4 = (f >> 6) * 4;
        float4 q4 = *(const float4*)(Qg + r * 64 + k4);
        sQ[(k4 + 0) * 64 + r] = q4.x;
        sQ[(k4 + 1) * 64 + r] = q4.y;
        sQ[(k4 + 2) * 64 + r] = q4.z;
        sQ[(k4 + 3) * 64 + r] = q4.w;
    }
    if (tid < 64) sq0[tid] = g_q0[bh * T_ + qt * 64 + tid];

    float O[4][4] = {};
    float mrow[4] = {-1e30f, -1e30f, -1e30f, -1e30f};
    float lrow[4] = {};

    for (int st = 0; st <= qt; st++) {
        const float* Kt = Kg + (size_t)st * 64 * 64;
        const float* Vt = Vg + (size_t)st * 64 * 64;
#pragma unroll
        for (int i = 0; i < 4; i++) {
            int f  = tid + i * 256;
            int r  = f & 63;
            int k4 = (f >> 6) * 4;
            float4 k4v = *(const float4*)(Kt + r * 64 + k4);
            sK[(k4 + 0) * 64 + r] = k4v.x;
            sK[(k4 + 1) * 64 + r] = k4v.y;
            sK[(k4 + 2) * 64 + r] = k4v.z;
            sK[(k4 + 3) * 64 + r] = k4v.w;
            int s  = f >> 4;
            int d4 = (f & 15) * 4;
            *(float4*)(sV + s * 64 + d4) = *(const float4*)(Vt + s * 64 + d4);
        }
        if (tid < 64) sk0[tid] = g_k0[bh * T_ + st * 64 + tid];
        __syncthreads();

        float S[4][4] = {};
#pragma unroll 8
        for (int kk = 0; kk < 64; kk++) {
            float4 a  = *(const float4*)(sQ + kk * 64 + row0);
            float4 bb = *(const float4*)(sK + kk * 64 + col0);
            float ar[4] = {a.x, a.y, a.z, a.w};
            float br[4] = {bb.x, bb.y, bb.z, bb.w};
#pragma unroll
            for (int i = 0; i < 4; i++)
#pragma unroll
                for (int j = 0; j < 4; j++)
                    S[i][j] = fmaf(ar[i], br[j], S[i][j]);
        }

        float q0r[4], k0c[4];
#pragma unroll
        for (int i = 0; i < 4; i++) q0r[i] = sq0[row0 + i];
#pragma unroll
        for (int j = 0; j < 4; j++) k0c[j] = sk0[col0 + j];
        const bool diag = (st == qt);
#pragma unroll
        for (int i = 0; i < 4; i++) {
#pragma unroll
            for (int j = 0; j < 4; j++) {
                float inner = S[i][j] - q0r[i] * k0c[j];
                float arg   = fmaxf(-inner * invk, 1.0f + 1e-6f);
                float tm    = arg - 1.0f;
                float dis   = sqk * __logf(arg + sqrtf(tm * (arg + 1.0f)));
                float w     = 1.0f / (1e-6f + dis);
                if (diag && (col0 + j) > (row0 + i)) w = -1e30f;
                S[i][j] = w;
            }
        }

#pragma unroll
        for (int i = 0; i < 4; i++) {
            float rmax = fmaxf(fmaxf(S[i][0], S[i][1]), fmaxf(S[i][2], S[i][3]));
#pragma unroll
            for (int off = 1; off < 16; off <<= 1)
                rmax = fmaxf(rmax, __shfl_xor_sync(0xffffffffu, rmax, off));
            float nm = fmaxf(mrow[i], rmax);
            float alpha = __expf(mrow[i] - nm);
            mrow[i] = nm;
            float rsum = 0.0f;
#pragma unroll
            for (int j = 0; j < 4; j++) {
                float p = __expf(S[i][j] - nm);
                S[i][j] = p;
                rsum += p;
            }
#pragma unroll
            for (int off = 1; off < 16; off <<= 1)
                rsum += __shfl_xor_sync(0xffffffffu, rsum, off);
            lrow[i] = lrow[i] * alpha + rsum;
#pragma unroll
            for (int j = 0; j < 4; j++) O[i][j] *= alpha;
        }

#pragma unroll
        for (int i = 0; i < 4; i++)
            *(float4*)(sP + (row0 + i) * 64 + col0) =
                make_float4(S[i][0], S[i][1], S[i][2], S[i][3]);
        __syncthreads();

#pragma unroll 8
        for (int s = 0; s < 64; s++) {
            float4 v = *(const float4*)(sV + s * 64 + col0);
            float vr[4] = {v.x, v.y, v.z, v.w};
            float pr[4];
#pragma unroll
            for (int i = 0; i < 4; i++) pr[i] = sP[(row0 + i) * 64 + s];
#pragma unroll
            for (int i = 0; i < 4; i++)
#pragma unroll
                for (int j = 0; j < 4; j++)
                    O[i][j] = fmaf(pr[i], vr[j], O[i][j]);
        }
        __syncthreads();
    }

#pragma unroll
    for (int i = 0; i < 4; i++) {
        float inv = 1.0f / lrow[i];
        int r = qt * 64 + row0 + i;
        float4 o = make_float4(O[i][0] * inv, O[i][1] * inv,
                               O[i][2] * inv, O[i][3] * inv);
        *(float4*)(g_o + ((size_t)b * T_ + r) * C_ + h * 64 + col0) = o;
    }
}

// ---------------- launch ------------------------------------------------------
extern "C" void kernel_launch(void* const* d_in, const int* in_sizes, int n_in,
                              void* d_out, int out_size)
{
    const float* x    = (const float*)d_in[0];
    const float* Wqkv = (const float*)d_in[1];
    const float* Wout = (const float*)d_in[2];
    const float* hyp  = (const float*)d_in[3];
    float* out = (float*)d_out;

    static float* p_qkv = nullptr;
    static float* p_o = nullptr;
    if (!p_qkv) {
        cudaGetSymbolAddress((void**)&p_qkv, g_qkv);
        cudaGetSymbolAddress((void**)&p_o, g_o);
        cudaFuncSetAttribute(attn_flash,
                             cudaFuncAttributeMaxDynamicSharedMemorySize,
                             (4 * 4096 + 128) * sizeof(float));
        cudaFuncSetAttribute(gemm_mma,
                             cudaFuncAttributeMaxDynamicSharedMemorySize, 2 * GST);
    }

    // 1) qkv = x @ W_qkv^T : (4096 x 1024) @ (1024 x 3072)
    gemm_mma<<<dim3(3072 / 128, 4096 / 128), 256, 2 * GST>>>(x, Wqkv, p_qkv, 4096, 3072, 1024);

    // 2) RoPE + split + norms
    rope_split<<<B_ * T_ * H_, 32>>>(p_qkv, hyp);

    // 3) flash attention (64x64 tiles)
    attn_flash<<<dim3(T_ / 64, H_, B_), 256, (4 * 4096 + 128) * sizeof(float)>>>(hyp);

    // 4) out = o @ W_out^T : (4096 x 1024) @ (1024 x 1024)
    gemm_mma<<<dim3(1024 / 128, 4096 / 128), 256, 2 * GST>>>(p_o, Wout, out, 4096, 1024, 1024);
}

// round 6
// speedup vs baseline: 5.5170x; 1.3691x over previous
#include <cuda_runtime.h>
#include <cuda_bf16.h>
#include <math.h>
#include <stdint.h>

#define B_ 4
#define T_ 1024
#define C_ 1024
#define H_ 16
#define HD 64

// ---------------- scratch (static device globals; no allocation) -------------
__device__ __align__(16) float g_qkv[(size_t)4096 * 3072];
__device__ __align__(16) float g_q[(size_t)4096 * 1024];
__device__ __align__(16) float g_k[(size_t)4096 * 1024];
__device__ __align__(16) float g_v[(size_t)4096 * 1024];
__device__ float g_q0[(size_t)B_ * H_ * T_];
__device__ float g_k0[(size_t)B_ * H_ * T_];
__device__ __align__(16) float g_o[(size_t)4096 * 1024];

// ---------------- helpers ------------------------------------------------------
__device__ __forceinline__ uint32_t smem_u32(const void* p) {
    uint32_t a;
    asm("{ .reg .u64 t; cvta.to.shared.u64 t, %1; cvt.u32.u64 %0, t; }" : "=r"(a) : "l"(p));
    return a;
}
__device__ __forceinline__ void ldm_x4(uint32_t& r0, uint32_t& r1, uint32_t& r2, uint32_t& r3,
                                       uint32_t addr) {
    asm volatile("ldmatrix.sync.aligned.m8n8.x4.shared.b16 {%0,%1,%2,%3}, [%4];"
                 : "=r"(r0), "=r"(r1), "=r"(r2), "=r"(r3) : "r"(addr));
}
__device__ __forceinline__ void ldm_x2(uint32_t& r0, uint32_t& r1, uint32_t addr) {
    asm volatile("ldmatrix.sync.aligned.m8n8.x2.shared.b16 {%0,%1}, [%2];"
                 : "=r"(r0), "=r"(r1) : "r"(addr));
}
__device__ __forceinline__ void ldm_x2t(uint32_t& r0, uint32_t& r1, uint32_t addr) {
    asm volatile("ldmatrix.sync.aligned.m8n8.x2.trans.shared.b16 {%0,%1}, [%2];"
                 : "=r"(r0), "=r"(r1) : "r"(addr));
}
__device__ __forceinline__ void mma16816(float* d, const uint32_t* a, const uint32_t* b) {
    asm volatile("mma.sync.aligned.m16n8k16.row.col.f32.bf16.bf16.f32 "
                 "{%0,%1,%2,%3}, {%4,%5,%6,%7}, {%8,%9}, {%0,%1,%2,%3};"
                 : "+f"(d[0]), "+f"(d[1]), "+f"(d[2]), "+f"(d[3])
                 : "r"(a[0]), "r"(a[1]), "r"(a[2]), "r"(a[3]), "r"(b[0]), "r"(b[1]));
}
__device__ __forceinline__ void split2(float x, float y, uint32_t& hi, uint32_t& lo) {
    __nv_bfloat16 hx = __float2bfloat16(x), hy = __float2bfloat16(y);
    __nv_bfloat162 h(hx, hy);
    __nv_bfloat162 l(__float2bfloat16(x - __bfloat162float(hx)),
                     __float2bfloat16(y - __bfloat162float(hy)));
    hi = *(uint32_t*)&h;
    lo = *(uint32_t*)&l;
}

// ---------------- tensor-core GEMM (unchanged from R4) ------------------------
#define GST 40960
#define ROWB 80

__global__ __launch_bounds__(256) void gemm_mma(
    const float* __restrict__ A, const float* __restrict__ B,
    float* __restrict__ C, int M, int N, int K)
{
    extern __shared__ __align__(128) char smem[];
    const uint32_t sb = smem_u32(smem);
    const int tid = threadIdx.x;
    const int lane = tid & 31, warp = tid >> 5;
    const int wm = warp >> 2, wn = warp & 3;
    const int bm = blockIdx.y * 128, bn = blockIdx.x * 128;
    const int NC = K / 32;

    const int lrow = tid >> 3;
    const int lslot = tid & 7;

    float4 pA[4], pB[4];
#pragma unroll
    for (int j = 0; j < 4; j++) {
        pA[j] = *(const float4*)(A + (size_t)(bm + lrow + j * 32) * K + lslot * 4);
        pB[j] = *(const float4*)(B + (size_t)(bn + lrow + j * 32) * K + lslot * 4);
    }

    auto sts_all = [&](int st) {
#pragma unroll
        for (int j = 0; j < 4; j++) {
            int r = lrow + j * 32;
            uint32_t h0, l0, h1, l1;
            split2(pA[j].x, pA[j].y, h0, l0);
            split2(pA[j].z, pA[j].w, h1, l1);
            *(uint2*)(smem + (st * GST) + r * ROWB + lslot * 8) = make_uint2(h0, h1);
            *(uint2*)(smem + (st * GST) + 10240 + r * ROWB + lslot * 8) = make_uint2(l0, l1);
            split2(pB[j].x, pB[j].y, h0, l0);
            split2(pB[j].z, pB[j].w, h1, l1);
            *(uint2*)(smem + (st * GST) + 20480 + r * ROWB + lslot * 8) = make_uint2(h0, h1);
            *(uint2*)(smem + (st * GST) + 30720 + r * ROWB + lslot * 8) = make_uint2(l0, l1);
        }
    };

    sts_all(0);
    __syncthreads();

    float acc[16][4] = {};

    const uint32_t aoff = (uint32_t)((wm * 64 + (lane & 15)) * ROWB + (lane >> 4) * 16);
    const uint32_t boff = (uint32_t)((wn * 32 + (lane & 7)) * ROWB + ((lane >> 3) & 1) * 16);

    for (int i = 0; i < NC; i++) {
        const int s = i & 1;
        if (i + 1 < NC) {
            const int k0 = (i + 1) * 32;
#pragma unroll
            for (int j = 0; j < 4; j++) {
                pA[j] = *(const float4*)(A + (size_t)(bm + lrow + j * 32) * K + k0 + lslot * 4);
                pB[j] = *(const float4*)(B + (size_t)(bn + lrow + j * 32) * K + k0 + lslot * 4);
            }
        }

        const uint32_t sAh = sb + s * GST;
        const uint32_t sAl = sAh + 10240;
        const uint32_t sBh = sAh + 20480;
        const uint32_t sBl = sAh + 30720;

#pragma unroll
        for (int kk = 0; kk < 2; kk++) {
            uint32_t ah[4][4], al[4][4], bh[4][2], bl[4][2];
#pragma unroll
            for (int am = 0; am < 4; am++) {
                uint32_t ad = aoff + am * 16 * ROWB + kk * 32;
                ldm_x4(ah[am][0], ah[am][1], ah[am][2], ah[am][3], sAh + ad);
                ldm_x4(al[am][0], al[am][1], al[am][2], al[am][3], sAl + ad);
            }
#pragma unroll
            for (int bt = 0; bt < 4; bt++) {
                uint32_t bd = boff + bt * 8 * ROWB + kk * 32;
                ldm_x2(bh[bt][0], bh[bt][1], sBh + bd);
                ldm_x2(bl[bt][0], bl[bt][1], sBl + bd);
            }
#pragma unroll
            for (int am = 0; am < 4; am++)
#pragma unroll
                for (int bt = 0; bt < 4; bt++) {
                    mma16816(acc[am * 4 + bt], ah[am], bh[bt]);
                    mma16816(acc[am * 4 + bt], ah[am], bl[bt]);
                    mma16816(acc[am * 4 + bt], al[am], bh[bt]);
                }
        }

        if (i + 1 < NC) {
            sts_all(s ^ 1);
        }
        __syncthreads();
    }

    const int er = bm + wm * 64 + (lane >> 2);
    const int ec = bn + wn * 32 + (lane & 3) * 2;
#pragma unroll
    for (int am = 0; am < 4; am++)
#pragma unroll
        for (int bt = 0; bt < 4; bt++) {
            float* d = acc[am * 4 + bt];
            int r = er + am * 16;
            int c = ec + bt * 8;
            *(float2*)(C + (size_t)r * N + c) = make_float2(d[0], d[1]);
            *(float2*)(C + (size_t)(r + 8) * N + c) = make_float2(d[2], d[3]);
        }
}

// ---------------- RoPE + split to [B,H,T,hd] + q0/k0 norms -------------------
__global__ void rope_split(const float* __restrict__ qkv, const float* __restrict__ hyp)
{
    int bi = blockIdx.x;
    int h = bi % H_;
    int t = (bi / H_) % T_;
    int b = bi / (H_ * T_);
    int j = threadIdx.x;

    const float* src = qkv + (size_t)(b * T_ + t) * (3 * C_) + h * HD;
    float kc = hyp[h];

    float inv = powf(10000.0f, -(float)(2 * j) / 64.0f);
    float fr = (float)t * inv;
    float cs = cosf(fr);
    float sn = sinf(fr);

    size_t dst = ((size_t)(b * H_ + h) * T_ + t) * HD;

    float q1 = src[j], q2 = src[j + 32];
    float qo1 = q1 * cs + q2 * sn;
    float qo2 = -q1 * sn + q2 * cs;
    g_q[dst + j] = qo1;
    g_q[dst + j + 32] = qo2;

    float k1 = src[C_ + j], k2 = src[C_ + j + 32];
    float ko1 = k1 * cs + k2 * sn;
    float ko2 = -k1 * sn + k2 * cs;
    g_k[dst + j] = ko1;
    g_k[dst + j + 32] = ko2;

    g_v[dst + j] = src[2 * C_ + j];
    g_v[dst + j + 32] = src[2 * C_ + j + 32];

    float sq = qo1 * qo1 + qo2 * qo2;
    float sk = ko1 * ko1 + ko2 * ko2;
#pragma unroll
    for (int off = 16; off; off >>= 1) {
        sq += __shfl_xor_sync(0xffffffffu, sq, off);
        sk += __shfl_xor_sync(0xffffffffu, sk, off);
    }
    if (j == 0) {
        size_t r = (size_t)(b * H_ + h) * T_ + t;
        g_q0[r] = sqrtf(kc + sq);
        g_k0[r] = sqrtf(kc + sk);
    }
}

// ---------------- per-score hyperbolic transform (4 MUFU) ---------------------
__device__ __forceinline__ float score_p(float s, float q0, float k0,
                                         float invk, float c1) {
    float inner = s - q0 * k0;
    float arg = fmaxf(-inner * invk, 1.000001f);
    float t = fmaf(arg, arg, -1.0f);
    float sq; asm("sqrt.approx.f32 %0, %1;" : "=f"(sq) : "f"(t));
    float y = arg + sq;
    float lg; asm("lg2.approx.f32 %0, %1;" : "=f"(lg) : "f"(y));
    float u = fmaf(c1, lg, 1e-6f);            // eps + sqrt(k)*acosh(arg)
    float w; asm("rcp.approx.f32 %0, %1;" : "=f"(w) : "f"(u));
    w = fminf(w, 60.0f);                       // overflow guard (true w <= ~1)
    float p; asm("ex2.approx.f32 %0, %1;" : "=f"(p) : "f"(w * 1.44269504f));
    return p;
}

// ---------------- tensorized attention: 128 q-rows x 64-key tiles -------------
// 8 warps; warp w owns q-rows [w*16, w*16+16). No max-subtraction softmax
// (weights bounded by (kc+ab)^2 identity), P stays in registers.
#define AROWB 144
#define SQH 0
#define SQL 18432
#define SKH 36864
#define SKL 46080
#define SVH 55296
#define SVL 64512
#define SK0 73728
#define ATT_SMEM 73984

__global__ __launch_bounds__(256) void attn_mma(const float* __restrict__ hyp)
{
    extern __shared__ __align__(128) char smem[];
    const uint32_t sb = smem_u32(smem);
    const int tid = threadIdx.x;
    const int lane = tid & 31, warp = tid >> 5;
    const int qt = (int)gridDim.x - 1 - (int)blockIdx.x;   // big tiles first
    const int h = blockIdx.y, b = blockIdx.z;
    const size_t bh = (size_t)b * H_ + h;
    const float* Qg = g_q + (bh * T_ + (size_t)qt * 128) * HD;
    const float* Kg = g_k + bh * T_ * HD;
    const float* Vg = g_v + bh * T_ * HD;
    const float* k0g = g_k0 + bh * T_;

    const float kc   = hyp[h];
    const float invk = 1.0f / kc;
    const float c1   = sqrtf(kc) * 0.69314718056f;   // sqrt(k)*ln2

    // ---- Q tile -> split bf16 -> smem
#pragma unroll
    for (int i = 0; i < 8; i++) {
        int idx = tid + i * 256;                 // 2048 float4 slots
        int row = idx >> 4, c4 = idx & 15;
        float4 q4 = *(const float4*)(Qg + row * 64 + c4 * 4);
        uint32_t h0, l0, h1, l1;
        split2(q4.x, q4.y, h0, l0);
        split2(q4.z, q4.w, h1, l1);
        *(uint2*)(smem + SQH + row * AROWB + c4 * 8) = make_uint2(h0, h1);
        *(uint2*)(smem + SQL + row * AROWB + c4 * 8) = make_uint2(l0, l1);
    }
    __syncthreads();

    // ---- Q fragments (held in registers for whole kernel)
    uint32_t qa_h[4][4], qa_l[4][4];
    const uint32_t qoff = (uint32_t)((warp * 16 + (lane & 15)) * AROWB + (lane >> 4) * 16);
#pragma unroll
    for (int g = 0; g < 4; g++) {
        ldm_x4(qa_h[g][0], qa_h[g][1], qa_h[g][2], qa_h[g][3], sb + SQH + qoff + g * 32);
        ldm_x4(qa_l[g][0], qa_l[g][1], qa_l[g][2], qa_l[g][3], sb + SQL + qoff + g * 32);
    }

    const int r_in  = lane >> 2;
    const int cpair = (lane & 3) * 2;
    const int qr0 = qt * 128 + warp * 16 + r_in;
    const int qr1 = qr0 + 8;
    const float q00 = g_q0[bh * T_ + qr0];
    const float q01 = g_q0[bh * T_ + qr1];

    const int ntile = 2 * qt + 2;

    // prefetch tile 0 (K, V, k0)
    float4 pk[4], pv[4];
    float pk0 = 0.0f;
#pragma unroll
    for (int i = 0; i < 4; i++) {
        int idx = tid + i * 256;
        int row = idx >> 4, c4 = idx & 15;
        pk[i] = *(const float4*)(Kg + row * 64 + c4 * 4);
        pv[i] = *(const float4*)(Vg + row * 64 + c4 * 4);
    }
    if (tid < 64) pk0 = k0g[tid];

    float O[8][4] = {};
    float ls0 = 0.0f, ls1 = 0.0f;

    for (int st = 0; st < ntile; st++) {
        // stage K/V/k0 into smem (split bf16)
#pragma unroll
        for (int i = 0; i < 4; i++) {
            int idx = tid + i * 256;
            int row = idx >> 4, c4 = idx & 15;
            uint32_t h0, l0, h1, l1;
            split2(pk[i].x, pk[i].y, h0, l0);
            split2(pk[i].z, pk[i].w, h1, l1);
            *(uint2*)(smem + SKH + row * AROWB + c4 * 8) = make_uint2(h0, h1);
            *(uint2*)(smem + SKL + row * AROWB + c4 * 8) = make_uint2(l0, l1);
            split2(pv[i].x, pv[i].y, h0, l0);
            split2(pv[i].z, pv[i].w, h1, l1);
            *(uint2*)(smem + SVH + row * AROWB + c4 * 8) = make_uint2(h0, h1);
            *(uint2*)(smem + SVL + row * AROWB + c4 * 8) = make_uint2(l0, l1);
        }
        if (tid < 64) *(float*)(smem + SK0 + tid * 4) = pk0;

        // prefetch next tile
        if (st + 1 < ntile) {
            const float* Kn = Kg + (size_t)(st + 1) * 64 * 64;
            const float* Vn = Vg + (size_t)(st + 1) * 64 * 64;
#pragma unroll
            for (int i = 0; i < 4; i++) {
                int idx = tid + i * 256;
                int row = idx >> 4, c4 = idx & 15;
                pk[i] = *(const float4*)(Kn + row * 64 + c4 * 4);
                pv[i] = *(const float4*)(Vn + row * 64 + c4 * 4);
            }
            if (tid < 64) pk0 = k0g[(st + 1) * 64 + tid];
        }
        __syncthreads();

        const bool maskT = (st >= 2 * qt);
        const int key_base = st * 64;

        uint32_t pa_h[4][4], pa_l[4][4];

        // ---- S = Q K^T, transform, pack P
#pragma unroll
        for (int nt = 0; nt < 8; nt++) {
            float sacc[4] = {};
            const uint32_t kb = (uint32_t)((nt * 8 + (lane & 7)) * AROWB +
                                           ((lane >> 3) & 1) * 16);
#pragma unroll
            for (int g = 0; g < 4; g++) {
                uint32_t kh[2], kl[2];
                ldm_x2(kh[0], kh[1], sb + SKH + kb + g * 32);
                ldm_x2(kl[0], kl[1], sb + SKL + kb + g * 32);
                mma16816(sacc, qa_h[g], kh);
                mma16816(sacc, qa_h[g], kl);
                mma16816(sacc, qa_l[g], kh);
            }

            float2 k0p = *(const float2*)(smem + SK0 + (nt * 8 + cpair) * 4);
            const int keyc = key_base + nt * 8 + cpair;

            float p0 = score_p(sacc[0], q00, k0p.x, invk, c1);
            float p1 = score_p(sacc[1], q00, k0p.y, invk, c1);
            float p2 = score_p(sacc[2], q01, k0p.x, invk, c1);
            float p3 = score_p(sacc[3], q01, k0p.y, invk, c1);
            if (maskT) {
                if (keyc     > qr0) p0 = 0.0f;
                if (keyc + 1 > qr0) p1 = 0.0f;
                if (keyc     > qr1) p2 = 0.0f;
                if (keyc + 1 > qr1) p3 = 0.0f;
            }
            ls0 += p0 + p1;
            ls1 += p2 + p3;

            const int g = nt >> 1;
            const int rb = (nt & 1) * 2;
            split2(p0, p1, pa_h[g][rb + 0], pa_l[g][rb + 0]);
            split2(p2, p3, pa_h[g][rb + 1], pa_l[g][rb + 1]);
        }

        // fix A-frag register order: regs must be {a0=(r,klo), a1=(r+8,klo), a2=(r,khi), a3=(r+8,khi)}
        // our fill order above gives [0]=(r,klo) [1]=(r+8,klo) [2]=(r,khi) [3]=(r+8,khi)  — correct.

        // ---- O += P V  (V via ldmatrix.trans from row-major)
#pragma unroll
        for (int dt = 0; dt < 8; dt++) {
#pragma unroll
            for (int g = 0; g < 4; g++) {
                const uint32_t vo = (uint32_t)((g * 16 + (lane & 15)) * AROWB + dt * 16);
                uint32_t vh[2], vl[2];
                ldm_x2t(vh[0], vh[1], sb + SVH + vo);
                ldm_x2t(vl[0], vl[1], sb + SVL + vo);
                mma16816(O[dt], pa_h[g], vh);
                mma16816(O[dt], pa_h[g], vl);
                mma16816(O[dt], pa_l[g], vh);
            }
        }
        __syncthreads();
    }

    // ---- normalize and store
    ls0 += __shfl_xor_sync(0xffffffffu, ls0, 1);
    ls0 += __shfl_xor_sync(0xffffffffu, ls0, 2);
    ls1 += __shfl_xor_sync(0xffffffffu, ls1, 1);
    ls1 += __shfl_xor_sync(0xffffffffu, ls1, 2);
    const float n0 = 1.0f / ls0;
    const float n1 = 1.0f / ls1;

    float* orow0 = g_o + ((size_t)b * T_ + qr0) * C_ + h * 64;
    float* orow1 = g_o + ((size_t)b * T_ + qr1) * C_ + h * 64;
#pragma unroll
    for (int dt = 0; dt < 8; dt++) {
        const int c = dt * 8 + cpair;
        *(float2*)(orow0 + c) = make_float2(O[dt][0] * n0, O[dt][1] * n0);
        *(float2*)(orow1 + c) = make_float2(O[dt][2] * n1, O[dt][3] * n1);
    }
}

// ---------------- launch ------------------------------------------------------
extern "C" void kernel_launch(void* const* d_in, const int* in_sizes, int n_in,
                              void* d_out, int out_size)
{
    const float* x    = (const float*)d_in[0];
    const float* Wqkv = (const float*)d_in[1];
    const float* Wout = (const float*)d_in[2];
    const float* hyp  = (const float*)d_in[3];
    float* out = (float*)d_out;

    static float* p_qkv = nullptr;
    static float* p_o = nullptr;
    if (!p_qkv) {
        cudaGetSymbolAddress((void**)&p_qkv, g_qkv);
        cudaGetSymbolAddress((void**)&p_o, g_o);
        cudaFuncSetAttribute(gemm_mma,
                             cudaFuncAttributeMaxDynamicSharedMemorySize, 2 * GST);
        cudaFuncSetAttribute(attn_mma,
                             cudaFuncAttributeMaxDynamicSharedMemorySize, ATT_SMEM);
    }

    // 1) qkv = x @ W_qkv^T
    gemm_mma<<<dim3(3072 / 128, 4096 / 128), 256, 2 * GST>>>(x, Wqkv, p_qkv, 4096, 3072, 1024);

    // 2) RoPE + split + norms
    rope_split<<<B_ * T_ * H_, 32>>>(p_qkv, hyp);

    // 3) tensorized attention (128 q-rows per CTA)
    attn_mma<<<dim3(T_ / 128, H_, B_), 256, ATT_SMEM>>>(hyp);

    // 4) out = o @ W_out^T
    gemm_mma<<<dim3(1024 / 128, 4096 / 128), 256, 2 * GST>>>(p_o, Wout, out, 4096, 1024, 1024);
}

// round 8
// speedup vs baseline: 5.5572x; 1.0073x over previous
#include <cuda_runtime.h>
#include <cuda_bf16.h>
#include <math.h>
#include <stdint.h>

#define B_ 4
#define T_ 1024
#define C_ 1024
#define H_ 16
#define HD 64

// ---------------- scratch (static device globals; no allocation) -------------
__device__ __align__(16) float g_qkv[(size_t)4096 * 3072];
__device__ float g_q0[(size_t)B_ * H_ * T_];
__device__ float g_k0[(size_t)B_ * H_ * T_];
// split bf16 operand buffers
__device__ __align__(16) __nv_bfloat16 g_xh[(size_t)4096 * 1024];
__device__ __align__(16) __nv_bfloat16 g_xl[(size_t)4096 * 1024];
__device__ __align__(16) __nv_bfloat16 g_w1h[(size_t)3072 * 1024];
__device__ __align__(16) __nv_bfloat16 g_w1l[(size_t)3072 * 1024];
__device__ __align__(16) __nv_bfloat16 g_w2h[(size_t)1024 * 1024];
__device__ __align__(16) __nv_bfloat16 g_w2l[(size_t)1024 * 1024];
__device__ __align__(16) __nv_bfloat16 g_qh[(size_t)4096 * 1024];
__device__ __align__(16) __nv_bfloat16 g_ql[(size_t)4096 * 1024];
__device__ __align__(16) __nv_bfloat16 g_kh[(size_t)4096 * 1024];
__device__ __align__(16) __nv_bfloat16 g_kl[(size_t)4096 * 1024];
__device__ __align__(16) __nv_bfloat16 g_vh[(size_t)4096 * 1024];
__device__ __align__(16) __nv_bfloat16 g_vl[(size_t)4096 * 1024];
__device__ __align__(16) __nv_bfloat16 g_oh[(size_t)4096 * 1024];
__device__ __align__(16) __nv_bfloat16 g_ol[(size_t)4096 * 1024];

// ---------------- helpers ------------------------------------------------------
__device__ __forceinline__ uint32_t smem_u32(const void* p) {
    uint32_t a;
    asm("{ .reg .u64 t; cvta.to.shared.u64 t, %1; cvt.u32.u64 %0, t; }" : "=r"(a) : "l"(p));
    return a;
}
#define CP_ASYNC16(d, s)  asm volatile("cp.async.cg.shared.global [%0], [%1], 16;" :: "r"(d), "l"(s))
#define CP_COMMIT()       asm volatile("cp.async.commit_group;" ::: "memory")
#define CP_WAIT(n)        asm volatile("cp.async.wait_group %0;" :: "n"(n) : "memory")

__device__ __forceinline__ void ldm_x4(uint32_t& r0, uint32_t& r1, uint32_t& r2, uint32_t& r3,
                                       uint32_t addr) {
    asm volatile("ldmatrix.sync.aligned.m8n8.x4.shared.b16 {%0,%1,%2,%3}, [%4];"
                 : "=r"(r0), "=r"(r1), "=r"(r2), "=r"(r3) : "r"(addr));
}
__device__ __forceinline__ void ldm_x2(uint32_t& r0, uint32_t& r1, uint32_t addr) {
    asm volatile("ldmatrix.sync.aligned.m8n8.x2.shared.b16 {%0,%1}, [%2];"
                 : "=r"(r0), "=r"(r1) : "r"(addr));
}
__device__ __forceinline__ void ldm_x2t(uint32_t& r0, uint32_t& r1, uint32_t addr) {
    asm volatile("ldmatrix.sync.aligned.m8n8.x2.trans.shared.b16 {%0,%1}, [%2];"
                 : "=r"(r0), "=r"(r1) : "r"(addr));
}
__device__ __forceinline__ void mma16816(float* d, const uint32_t* a, const uint32_t* b) {
    asm volatile("mma.sync.aligned.m16n8k16.row.col.f32.bf16.bf16.f32 "
                 "{%0,%1,%2,%3}, {%4,%5,%6,%7}, {%8,%9}, {%0,%1,%2,%3};"
                 : "+f"(d[0]), "+f"(d[1]), "+f"(d[2]), "+f"(d[3])
                 : "r"(a[0]), "r"(a[1]), "r"(a[2]), "r"(a[3]), "r"(b[0]), "r"(b[1]));
}
__device__ __forceinline__ void split2(float x, float y, uint32_t& hi, uint32_t& lo) {
    __nv_bfloat16 hx = __float2bfloat16(x), hy = __float2bfloat16(y);
    __nv_bfloat162 h(hx, hy);
    __nv_bfloat162 l(__float2bfloat16(x - __bfloat162float(hx)),
                     __float2bfloat16(y - __bfloat162float(hy)));
    hi = *(uint32_t*)&h;
    lo = *(uint32_t*)&l;
}

// ---------------- fp32 -> bf16 hi/lo split (grid-stride) ----------------------
__global__ void cvt_split(const float* __restrict__ src,
                          __nv_bfloat16* __restrict__ hi,
                          __nv_bfloat16* __restrict__ lo, int n4)
{
    int i = blockIdx.x * blockDim.x + threadIdx.x;
    if (i >= n4) return;
    float4 v = ((const float4*)src)[i];
    uint32_t h0, l0, h1, l1;
    split2(v.x, v.y, h0, l0);
    split2(v.z, v.w, h1, l1);
    *(uint2*)(hi + (size_t)i * 4) = make_uint2(h0, h1);
    *(uint2*)(lo + (size_t)i * 4) = make_uint2(l0, l1);
}

// ---------------- GEMM: C[m][n]=sum_k A[m][k]*B[n][k], split bf16 inputs ------
// 128x128x32 tiles, 3-stage cp.async pipeline, 256 threads, 8 warps (64x32 each)
#define ROWB 80
#define GSTAGE 40960     // 4 tiles x 128 rows x 80 B
#define GSM (3 * GSTAGE)

__global__ __launch_bounds__(256) void gemm_bf(
    const __nv_bfloat16* __restrict__ Ah, const __nv_bfloat16* __restrict__ Al,
    const __nv_bfloat16* __restrict__ Bh, const __nv_bfloat16* __restrict__ Bl,
    float* __restrict__ C, int M, int N, int K)
{
    extern __shared__ __align__(128) char smem[];
    const uint32_t sb = smem_u32(smem);
    const int tid = threadIdx.x;
    const int lane = tid & 31, warp = tid >> 5;
    const int wm = warp >> 2, wn = warp & 3;
    const int bm = blockIdx.y * 128, bn = blockIdx.x * 128;
    const int NC = K / 32;

    // 128 rows x 32 bf16 = 64 B/row = 4 chunks/row; 512 chunks per sub-tile
    const int r0 = tid >> 2, cc0 = tid & 3;            // rows 0..63
    const int r1 = (tid + 256) >> 2;                   // rows 64..127

    auto issue_stage = [&](int slot, int k0) {
        const uint32_t st = sb + slot * GSTAGE;
        uint32_t d = st + r0 * ROWB + cc0 * 16;
        const size_t sa = (size_t)(bm + r0) * K + k0 + cc0 * 8;
        const size_t sbm = (size_t)(bn + r0) * K + k0 + cc0 * 8;
        CP_ASYNC16(d,         Ah + sa);
        CP_ASYNC16(d + 10240, Al + sa);
        CP_ASYNC16(d + 20480, Bh + sbm);
        CP_ASYNC16(d + 30720, Bl + sbm);
        uint32_t d2 = st + r1 * ROWB + cc0 * 16;
        const size_t sa2 = (size_t)(bm + r1) * K + k0 + cc0 * 8;
        const size_t sb2 = (size_t)(bn + r1) * K + k0 + cc0 * 8;
        CP_ASYNC16(d2,         Ah + sa2);
        CP_ASYNC16(d2 + 10240, Al + sa2);
        CP_ASYNC16(d2 + 20480, Bh + sb2);
        CP_ASYNC16(d2 + 30720, Bl + sb2);
    };

    issue_stage(0, 0);
    CP_COMMIT();
    issue_stage(1, 32);
    CP_COMMIT();

    float acc[16][4] = {};

    const uint32_t aoff = (uint32_t)((wm * 64 + (lane & 15)) * ROWB + (lane >> 4) * 16);
    const uint32_t boff = (uint32_t)((wn * 32 + (lane & 7)) * ROWB + ((lane >> 3) & 1) * 16);

    for (int i = 0; i < NC; i++) {
        CP_WAIT(1);                 // stage i resident
        __syncthreads();
        if (i + 2 < NC) issue_stage((i + 2) % 3, (i + 2) * 32);
        CP_COMMIT();

        const uint32_t sAh = sb + (i % 3) * GSTAGE;
        const uint32_t sAl = sAh + 10240;
        const uint32_t sBh = sAh + 20480;
        const uint32_t sBl = sAh + 30720;

#pragma unroll
        for (int kk = 0; kk < 2; kk++) {
            uint32_t ah[4][4], al[4][4], bh[4][2], bl[4][2];
#pragma unroll
            for (int am = 0; am < 4; am++) {
                uint32_t ad = aoff + am * 16 * ROWB + kk * 32;
                ldm_x4(ah[am][0], ah[am][1], ah[am][2], ah[am][3], sAh + ad);
                ldm_x4(al[am][0], al[am][1], al[am][2], al[am][3], sAl + ad);
            }
#pragma unroll
            for (int bt = 0; bt < 4; bt++) {
                uint32_t bd = boff + bt * 8 * ROWB + kk * 32;
                ldm_x2(bh[bt][0], bh[bt][1], sBh + bd);
                ldm_x2(bl[bt][0], bl[bt][1], sBl + bd);
            }
#pragma unroll
            for (int am = 0; am < 4; am++)
#pragma unroll
                for (int bt = 0; bt < 4; bt++) {
                    mma16816(acc[am * 4 + bt], ah[am], bh[bt]);
                    mma16816(acc[am * 4 + bt], ah[am], bl[bt]);
                    mma16816(acc[am * 4 + bt], al[am], bh[bt]);
                }
        }
        __syncthreads();
    }

    const int er = bm + wm * 64 + (lane >> 2);
    const int ec = bn + wn * 32 + (lane & 3) * 2;
#pragma unroll
    for (int am = 0; am < 4; am++)
#pragma unroll
        for (int bt = 0; bt < 4; bt++) {
            float* d = acc[am * 4 + bt];
            int r = er + am * 16;
            int c = ec + bt * 8;
            *(float2*)(C + (size_t)r * N + c) = make_float2(d[0], d[1]);
            *(float2*)(C + (size_t)(r + 8) * N + c) = make_float2(d[2], d[3]);
        }
}

// ---------------- RoPE + split bf16 q/k/v + q0/k0 norms -----------------------
__global__ void rope_split(const float* __restrict__ qkv, const float* __restrict__ hyp)
{
    int bi = blockIdx.x;
    int h = bi % H_;
    int t = (bi / H_) % T_;
    int b = bi / (H_ * T_);
    int j = threadIdx.x;

    const float* src = qkv + (size_t)(b * T_ + t) * (3 * C_) + h * HD;
    float kc = hyp[h];

    float inv = powf(10000.0f, -(float)(2 * j) / 64.0f);
    float fr = (float)t * inv;
    float cs = cosf(fr);
    float sn = sinf(fr);

    size_t dst = ((size_t)(b * H_ + h) * T_ + t) * HD;

    float q1 = src[j], q2 = src[j + 32];
    float qo1 = q1 * cs + q2 * sn;
    float qo2 = -q1 * sn + q2 * cs;
    float k1 = src[C_ + j], k2 = src[C_ + j + 32];
    float ko1 = k1 * cs + k2 * sn;
    float ko2 = -k1 * sn + k2 * cs;
    float v1 = src[2 * C_ + j], v2 = src[2 * C_ + j + 32];

    __nv_bfloat16 hh;
    hh = __float2bfloat16(qo1); g_qh[dst + j] = hh;
    g_ql[dst + j] = __float2bfloat16(qo1 - __bfloat162float(hh));
    hh = __float2bfloat16(qo2); g_qh[dst + j + 32] = hh;
    g_ql[dst + j + 32] = __float2bfloat16(qo2 - __bfloat162float(hh));
    hh = __float2bfloat16(ko1); g_kh[dst + j] = hh;
    g_kl[dst + j] = __float2bfloat16(ko1 - __bfloat162float(hh));
    hh = __float2bfloat16(ko2); g_kh[dst + j + 32] = hh;
    g_kl[dst + j + 32] = __float2bfloat16(ko2 - __bfloat162float(hh));
    hh = __float2bfloat16(v1); g_vh[dst + j] = hh;
    g_vl[dst + j] = __float2bfloat16(v1 - __bfloat162float(hh));
    hh = __float2bfloat16(v2); g_vh[dst + j + 32] = hh;
    g_vl[dst + j + 32] = __float2bfloat16(v2 - __bfloat162float(hh));

    float sq = qo1 * qo1 + qo2 * qo2;
    float sk = ko1 * ko1 + ko2 * ko2;
#pragma unroll
    for (int off = 16; off; off >>= 1) {
        sq += __shfl_xor_sync(0xffffffffu, sq, off);
        sk += __shfl_xor_sync(0xffffffffu, sk, off);
    }
    if (j == 0) {
        size_t r = (size_t)(b * H_ + h) * T_ + t;
        g_q0[r] = sqrtf(kc + sq);
        g_k0[r] = sqrtf(kc + sk);
    }
}

// ---------------- per-score hyperbolic transform (4 MUFU) ---------------------
__device__ __forceinline__ float score_p(float s, float q0, float k0,
                                         float invk, float c1) {
    float inner = s - q0 * k0;
    float arg = fmaxf(-inner * invk, 1.000001f);
    float t = fmaf(arg, arg, -1.0f);
    float sq; asm("sqrt.approx.f32 %0, %1;" : "=f"(sq) : "f"(t));
    float y = arg + sq;
    float lg; asm("lg2.approx.f32 %0, %1;" : "=f"(lg) : "f"(y));
    float u = fmaf(c1, lg, 1e-6f);
    float w; asm("rcp.approx.f32 %0, %1;" : "=f"(w) : "f"(u));
    w = fminf(w, 60.0f);
    float p; asm("ex2.approx.f32 %0, %1;" : "=f"(p) : "f"(w * 1.44269504f));
    return p;
}

// ---------------- tensorized attention, cp.async double-buffered --------------
// KV tile: 64 rows x 64 bf16 = 128 B/row = 8 chunks/row; 512 chunks per sub-tile
#define AROWB 144
#define SQH 0
#define SQL 18432
#define SKV 36864                 // 2 stages x 36864
#define SK0 110592                // 2 x 256 B
#define ATT_SMEM 111104

__global__ __launch_bounds__(256) void attn_mma(const float* __restrict__ hyp)
{
    extern __shared__ __align__(128) char smem[];
    const uint32_t sb = smem_u32(smem);
    const int tid = threadIdx.x;
    const int lane = tid & 31, warp = tid >> 5;
    const int qt = (int)gridDim.x - 1 - (int)blockIdx.x;
    const int h = blockIdx.y, b = blockIdx.z;
    const size_t bh = (size_t)b * H_ + h;
    const size_t qbase = (bh * T_ + (size_t)qt * 128) * HD;
    const size_t kvbase = bh * T_ * HD;
    const float* k0g = g_k0 + bh * T_;

    const float kc   = hyp[h];
    const float invk = 1.0f / kc;
    const float c1   = sqrtf(kc) * 0.69314718056f;

    // KV chunk coords: 8 chunks/row over 64 rows
    const int ar0 = tid >> 3, ac0 = tid & 7;          // rows 0..31
    const int ar1 = (tid + 256) >> 3;                 // rows 32..63

    // ---- issue Q loads (128 rows x 8 chunks = 1024 chunks; 4 per thread)
#pragma unroll
    for (int i = 0; i < 4; i++) {
        int ch = tid + i * 256;
        int row = ch >> 3, cc = ch & 7;
        uint32_t d = sb + SQH + row * AROWB + cc * 16;
        CP_ASYNC16(d, g_qh + qbase + row * 64 + cc * 8);
        CP_ASYNC16(d + (SQL - SQH), g_ql + qbase + row * 64 + cc * 8);
    }
    CP_COMMIT();

    auto issue_kv = [&](int slot, int st) {
        const uint32_t sk = sb + SKV + slot * 36864;
        const size_t tb = kvbase + (size_t)st * 64 * 64;
        uint32_t d0 = sk + ar0 * AROWB + ac0 * 16;
        const size_t s0 = tb + ar0 * 64 + ac0 * 8;
        CP_ASYNC16(d0,         g_kh + s0);
        CP_ASYNC16(d0 + 9216,  g_kl + s0);
        CP_ASYNC16(d0 + 18432, g_vh + s0);
        CP_ASYNC16(d0 + 27648, g_vl + s0);
        uint32_t d1 = sk + ar1 * AROWB + ac0 * 16;
        const size_t s1 = tb + ar1 * 64 + ac0 * 8;
        CP_ASYNC16(d1,         g_kh + s1);
        CP_ASYNC16(d1 + 9216,  g_kl + s1);
        CP_ASYNC16(d1 + 18432, g_vh + s1);
        CP_ASYNC16(d1 + 27648, g_vl + s1);
        if (tid < 16) CP_ASYNC16(sb + SK0 + slot * 256 + tid * 16,
                                 k0g + st * 64 + tid * 4);
    };

    const int ntile = 2 * qt + 2;
    issue_kv(0, 0);
    CP_COMMIT();

    // ---- wait for Q, load Q fragments
    CP_WAIT(1);
    __syncthreads();
    uint32_t qa_h[4][4], qa_l[4][4];
    const uint32_t qoff = (uint32_t)((warp * 16 + (lane & 15)) * AROWB + (lane >> 4) * 16);
#pragma unroll
    for (int g = 0; g < 4; g++) {
        ldm_x4(qa_h[g][0], qa_h[g][1], qa_h[g][2], qa_h[g][3], sb + SQH + qoff + g * 32);
        ldm_x4(qa_l[g][0], qa_l[g][1], qa_l[g][2], qa_l[g][3], sb + SQL + qoff + g * 32);
    }

    const int r_in  = lane >> 2;
    const int cpair = (lane & 3) * 2;
    const int qr0 = qt * 128 + warp * 16 + r_in;
    const int qr1 = qr0 + 8;
    const float q00 = g_q0[bh * T_ + qr0];
    const float q01 = g_q0[bh * T_ + qr1];

    float O[8][4] = {};
    float ls0 = 0.0f, ls1 = 0.0f;

    for (int st = 0; st < ntile; st++) {
        const int s = st & 1;
        CP_WAIT(0);              // stage st resident
        __syncthreads();
        if (st + 1 < ntile) issue_kv(s ^ 1, st + 1);
        CP_COMMIT();

        const uint32_t sKh = sb + SKV + s * 36864;
        const uint32_t sKl = sKh + 9216;
        const uint32_t sVh = sKh + 18432;
        const uint32_t sVl = sKh + 27648;
        const uint32_t k0off = SK0 + s * 256;

        const bool maskT = (st >= 2 * qt);
        const int key_base = st * 64;

        uint32_t pa_h[4][4], pa_l[4][4];

#pragma unroll
        for (int nt = 0; nt < 8; nt++) {
            float sacc[4] = {};
            const uint32_t kb = (uint32_t)((nt * 8 + (lane & 7)) * AROWB +
                                           ((lane >> 3) & 1) * 16);
#pragma unroll
            for (int g = 0; g < 4; g++) {
                uint32_t kh[2], kl[2];
                ldm_x2(kh[0], kh[1], sKh + kb + g * 32);
                ldm_x2(kl[0], kl[1], sKl + kb + g * 32);
                mma16816(sacc, qa_h[g], kh);
                mma16816(sacc, qa_h[g], kl);
                mma16816(sacc, qa_l[g], kh);
            }

            float2 k0p = *(const float2*)(smem + k0off + (nt * 8 + cpair) * 4);
            const int keyc = key_base + nt * 8 + cpair;

            float p0 = score_p(sacc[0], q00, k0p.x, invk, c1);
            float p1 = score_p(sacc[1], q00, k0p.y, invk, c1);
            float p2 = score_p(sacc[2], q01, k0p.x, invk, c1);
            float p3 = score_p(sacc[3], q01, k0p.y, invk, c1);
            if (maskT) {
                if (keyc     > qr0) p0 = 0.0f;
                if (keyc + 1 > qr0) p1 = 0.0f;
                if (keyc     > qr1) p2 = 0.0f;
                if (keyc + 1 > qr1) p3 = 0.0f;
            }
            ls0 += p0 + p1;
            ls1 += p2 + p3;

            const int g = nt >> 1;
            const int rb = (nt & 1) * 2;
            split2(p0, p1, pa_h[g][rb + 0], pa_l[g][rb + 0]);
            split2(p2, p3, pa_h[g][rb + 1], pa_l[g][rb + 1]);
        }

#pragma unroll
        for (int dt = 0; dt < 8; dt++) {
#pragma unroll
            for (int g = 0; g < 4; g++) {
                const uint32_t vo = (uint32_t)((g * 16 + (lane & 15)) * AROWB + dt * 16);
                uint32_t vh[2], vl[2];
                ldm_x2t(vh[0], vh[1], sVh + vo);
                ldm_x2t(vl[0], vl[1], sVl + vo);
                mma16816(O[dt], pa_h[g], vh);
                mma16816(O[dt], pa_h[g], vl);
                mma16816(O[dt], pa_l[g], vh);
            }
        }
        __syncthreads();
    }

    // ---- normalize and store split bf16
    ls0 += __shfl_xor_sync(0xffffffffu, ls0, 1);
    ls0 += __shfl_xor_sync(0xffffffffu, ls0, 2);
    ls1 += __shfl_xor_sync(0xffffffffu, ls1, 1);
    ls1 += __shfl_xor_sync(0xffffffffu, ls1, 2);
    const float n0 = 1.0f / ls0;
    const float n1 = 1.0f / ls1;

    const size_t o0 = ((size_t)b * T_ + qr0) * C_ + h * 64;
    const size_t o1 = ((size_t)b * T_ + qr1) * C_ + h * 64;
#pragma unroll
    for (int dt = 0; dt < 8; dt++) {
        const int c = dt * 8 + cpair;
        uint32_t hh, ll;
        split2(O[dt][0] * n0, O[dt][1] * n0, hh, ll);
        *(uint32_t*)(g_oh + o0 + c) = hh;
        *(uint32_t*)(g_ol + o0 + c) = ll;
        split2(O[dt][2] * n1, O[dt][3] * n1, hh, ll);
        *(uint32_t*)(g_oh + o1 + c) = hh;
        *(uint32_t*)(g_ol + o1 + c) = ll;
    }
}

// ---------------- launch ------------------------------------------------------
extern "C" void kernel_launch(void* const* d_in, const int* in_sizes, int n_in,
                              void* d_out, int out_size)
{
    const float* x    = (const float*)d_in[0];
    const float* Wqkv = (const float*)d_in[1];
    const float* Wout = (const float*)d_in[2];
    const float* hyp  = (const float*)d_in[3];
    float* out = (float*)d_out;

    static float* p_qkv = nullptr;
    static __nv_bfloat16 *p_xh, *p_xl, *p_w1h, *p_w1l, *p_w2h, *p_w2l, *p_oh, *p_ol;
    if (!p_qkv) {
        cudaGetSymbolAddress((void**)&p_qkv, g_qkv);
        cudaGetSymbolAddress((void**)&p_xh, g_xh);
        cudaGetSymbolAddress((void**)&p_xl, g_xl);
        cudaGetSymbolAddress((void**)&p_w1h, g_w1h);
        cudaGetSymbolAddress((void**)&p_w1l, g_w1l);
        cudaGetSymbolAddress((void**)&p_w2h, g_w2h);
        cudaGetSymbolAddress((void**)&p_w2l, g_w2l);
        cudaGetSymbolAddress((void**)&p_oh, g_oh);
        cudaGetSymbolAddress((void**)&p_ol, g_ol);
        cudaFuncSetAttribute(gemm_bf,
                             cudaFuncAttributeMaxDynamicSharedMemorySize, GSM);
        cudaFuncSetAttribute(attn_mma,
                             cudaFuncAttributeMaxDynamicSharedMemorySize, ATT_SMEM);
    }

    // 0) one-time split conversions (per launch)
    cvt_split<<<(4096 * 1024 / 4 + 255) / 256, 256>>>(x, p_xh, p_xl, 4096 * 1024 / 4);
    cvt_split<<<(3072 * 1024 / 4 + 255) / 256, 256>>>(Wqkv, p_w1h, p_w1l, 3072 * 1024 / 4);
    cvt_split<<<(1024 * 1024 / 4 + 255) / 256, 256>>>(Wout, p_w2h, p_w2l, 1024 * 1024 / 4);

    // 1) qkv = x @ W_qkv^T
    gemm_bf<<<dim3(3072 / 128, 4096 / 128), 256, GSM>>>(
        p_xh, p_xl, p_w1h, p_w1l, p_qkv, 4096, 3072, 1024);

    // 2) RoPE + split + norms
    rope_split<<<B_ * T_ * H_, 32>>>(p_qkv, hyp);

    // 3) tensorized attention
    attn_mma<<<dim3(T_ / 128, H_, B_), 256, ATT_SMEM>>>(hyp);

    // 4) out = o @ W_out^T
    gemm_bf<<<dim3(1024 / 128, 4096 / 128), 256, GSM>>>(
        p_oh, p_ol, p_w2h, p_w2l, out, 4096, 1024, 1024);
}

// round 9
// speedup vs baseline: 6.1943x; 1.1146x over previous
#include <cuda_runtime.h>
#include <cuda_bf16.h>
#include <math.h>
#include <stdint.h>

#define B_ 4
#define T_ 1024
#define C_ 1024
#define H_ 16
#define HD 64

// ---------------- scratch (static device globals; no allocation) -------------
__device__ __align__(16) float g_qkv[(size_t)4096 * 3072];
__device__ float g_q0[(size_t)B_ * H_ * T_];
__device__ float g_k0[(size_t)B_ * H_ * T_];
__device__ __align__(16) __nv_bfloat16 g_xh[(size_t)4096 * 1024];
__device__ __align__(16) __nv_bfloat16 g_xl[(size_t)4096 * 1024];
__device__ __align__(16) __nv_bfloat16 g_w1h[(size_t)3072 * 1024];
__device__ __align__(16) __nv_bfloat16 g_w1l[(size_t)3072 * 1024];
__device__ __align__(16) __nv_bfloat16 g_w2h[(size_t)1024 * 1024];
__device__ __align__(16) __nv_bfloat16 g_w2l[(size_t)1024 * 1024];
__device__ __align__(16) __nv_bfloat16 g_qh[(size_t)4096 * 1024];
__device__ __align__(16) __nv_bfloat16 g_ql[(size_t)4096 * 1024];
__device__ __align__(16) __nv_bfloat16 g_kh[(size_t)4096 * 1024];
__device__ __align__(16) __nv_bfloat16 g_kl[(size_t)4096 * 1024];
__device__ __align__(16) __nv_bfloat16 g_vh[(size_t)4096 * 1024];
__device__ __align__(16) __nv_bfloat16 g_vl[(size_t)4096 * 1024];
__device__ __align__(16) __nv_bfloat16 g_oh[(size_t)4096 * 1024];
__device__ __align__(16) __nv_bfloat16 g_ol[(size_t)4096 * 1024];

// ---------------- helpers ------------------------------------------------------
__device__ __forceinline__ uint32_t smem_u32(const void* p) {
    uint32_t a;
    asm("{ .reg .u64 t; cvta.to.shared.u64 t, %1; cvt.u32.u64 %0, t; }" : "=r"(a) : "l"(p));
    return a;
}
#define CP_ASYNC16(d, s)  asm volatile("cp.async.cg.shared.global [%0], [%1], 16;" :: "r"(d), "l"(s))
#define CP_COMMIT()       asm volatile("cp.async.commit_group;" ::: "memory")
#define CP_WAIT(n)        asm volatile("cp.async.wait_group %0;" :: "n"(n) : "memory")

__device__ __forceinline__ void ldm_x4(uint32_t& r0, uint32_t& r1, uint32_t& r2, uint32_t& r3,
                                       uint32_t addr) {
    asm volatile("ldmatrix.sync.aligned.m8n8.x4.shared.b16 {%0,%1,%2,%3}, [%4];"
                 : "=r"(r0), "=r"(r1), "=r"(r2), "=r"(r3) : "r"(addr));
}
__device__ __forceinline__ void ldm_x2(uint32_t& r0, uint32_t& r1, uint32_t addr) {
    asm volatile("ldmatrix.sync.aligned.m8n8.x2.shared.b16 {%0,%1}, [%2];"
                 : "=r"(r0), "=r"(r1) : "r"(addr));
}
__device__ __forceinline__ void ldm_x2t(uint32_t& r0, uint32_t& r1, uint32_t addr) {
    asm volatile("ldmatrix.sync.aligned.m8n8.x2.trans.shared.b16 {%0,%1}, [%2];"
                 : "=r"(r0), "=r"(r1) : "r"(addr));
}
__device__ __forceinline__ void mma16816(float* d, const uint32_t* a, const uint32_t* b) {
    asm volatile("mma.sync.aligned.m16n8k16.row.col.f32.bf16.bf16.f32 "
                 "{%0,%1,%2,%3}, {%4,%5,%6,%7}, {%8,%9}, {%0,%1,%2,%3};"
                 : "+f"(d[0]), "+f"(d[1]), "+f"(d[2]), "+f"(d[3])
                 : "r"(a[0]), "r"(a[1]), "r"(a[2]), "r"(a[3]), "r"(b[0]), "r"(b[1]));
}
__device__ __forceinline__ void split2(float x, float y, uint32_t& hi, uint32_t& lo) {
    __nv_bfloat16 hx = __float2bfloat16(x), hy = __float2bfloat16(y);
    __nv_bfloat162 h(hx, hy);
    __nv_bfloat162 l(__float2bfloat16(x - __bfloat162float(hx)),
                     __float2bfloat16(y - __bfloat162float(hy)));
    hi = *(uint32_t*)&h;
    lo = *(uint32_t*)&l;
}

// ---------------- fp32 -> bf16 hi/lo split (grid-stride) ----------------------
__global__ void cvt_split(const float* __restrict__ src,
                          __nv_bfloat16* __restrict__ hi,
                          __nv_bfloat16* __restrict__ lo, int n4)
{
    int i = blockIdx.x * blockDim.x + threadIdx.x;
    if (i >= n4) return;
    float4 v = ((const float4*)src)[i];
    uint32_t h0, l0, h1, l1;
    split2(v.x, v.y, h0, l0);
    split2(v.z, v.w, h1, l1);
    *(uint2*)(hi + (size_t)i * 4) = make_uint2(h0, h1);
    *(uint2*)(lo + (size_t)i * 4) = make_uint2(l0, l1);
}

// ---------------- GEMM: C[m][n]=sum_k A[m][k]*B[n][k], split bf16 inputs ------
// 128x128x32 tiles, 2-stage cp.async pipeline, 256 threads, 2 CTAs/SM
#define ROWB 80
#define GSTAGE 40960
#define GSM (2 * GSTAGE)     // 81920 -> two CTAs per SM

__global__ __launch_bounds__(256, 2) void gemm_bf(
    const __nv_bfloat16* __restrict__ Ah, const __nv_bfloat16* __restrict__ Al,
    const __nv_bfloat16* __restrict__ Bh, const __nv_bfloat16* __restrict__ Bl,
    float* __restrict__ C, int M, int N, int K)
{
    extern __shared__ __align__(128) char smem[];
    const uint32_t sb = smem_u32(smem);
    const int tid = threadIdx.x;
    const int lane = tid & 31, warp = tid >> 5;
    const int wm = warp >> 2, wn = warp & 3;
    const int bm = blockIdx.y * 128, bn = blockIdx.x * 128;
    const int NC = K / 32;

    const int r0 = tid >> 2, cc0 = tid & 3;            // rows 0..63
    const int r1 = (tid + 256) >> 2;                   // rows 64..127

    auto issue_stage = [&](int slot, int k0) {
        const uint32_t st = sb + slot * GSTAGE;
        uint32_t d = st + r0 * ROWB + cc0 * 16;
        const size_t sa = (size_t)(bm + r0) * K + k0 + cc0 * 8;
        const size_t sbm = (size_t)(bn + r0) * K + k0 + cc0 * 8;
        CP_ASYNC16(d,         Ah + sa);
        CP_ASYNC16(d + 10240, Al + sa);
        CP_ASYNC16(d + 20480, Bh + sbm);
        CP_ASYNC16(d + 30720, Bl + sbm);
        uint32_t d2 = st + r1 * ROWB + cc0 * 16;
        const size_t sa2 = (size_t)(bm + r1) * K + k0 + cc0 * 8;
        const size_t sb2 = (size_t)(bn + r1) * K + k0 + cc0 * 8;
        CP_ASYNC16(d2,         Ah + sa2);
        CP_ASYNC16(d2 + 10240, Al + sa2);
        CP_ASYNC16(d2 + 20480, Bh + sb2);
        CP_ASYNC16(d2 + 30720, Bl + sb2);
    };

    issue_stage(0, 0);
    CP_COMMIT();

    float acc[16][4] = {};

    const uint32_t aoff = (uint32_t)((wm * 64 + (lane & 15)) * ROWB + (lane >> 4) * 16);
    const uint32_t boff = (uint32_t)((wn * 32 + (lane & 7)) * ROWB + ((lane >> 3) & 1) * 16);

    for (int i = 0; i < NC; i++) {
        if (i > 0) __syncthreads();              // previous compute done -> other stage free
        if (i + 1 < NC) { issue_stage((i + 1) & 1, (i + 1) * 32); CP_COMMIT(); }
        if (i + 1 < NC) { CP_WAIT(1); } else { CP_WAIT(0); }
        __syncthreads();                          // stage i resident for all

        const uint32_t sAh = sb + (i & 1) * GSTAGE;
        const uint32_t sAl = sAh + 10240;
        const uint32_t sBh = sAh + 20480;
        const uint32_t sBl = sAh + 30720;

#pragma unroll
        for (int kk = 0; kk < 2; kk++) {
            uint32_t ah[4][4], al[4][4], bh[4][2], bl[4][2];
#pragma unroll
            for (int am = 0; am < 4; am++) {
                uint32_t ad = aoff + am * 16 * ROWB + kk * 32;
                ldm_x4(ah[am][0], ah[am][1], ah[am][2], ah[am][3], sAh + ad);
                ldm_x4(al[am][0], al[am][1], al[am][2], al[am][3], sAl + ad);
            }
#pragma unroll
            for (int bt = 0; bt < 4; bt++) {
                uint32_t bd = boff + bt * 8 * ROWB + kk * 32;
                ldm_x2(bh[bt][0], bh[bt][1], sBh + bd);
                ldm_x2(bl[bt][0], bl[bt][1], sBl + bd);
            }
#pragma unroll
            for (int am = 0; am < 4; am++)
#pragma unroll
                for (int bt = 0; bt < 4; bt++) {
                    mma16816(acc[am * 4 + bt], ah[am], bh[bt]);
                    mma16816(acc[am * 4 + bt], ah[am], bl[bt]);
                    mma16816(acc[am * 4 + bt], al[am], bh[bt]);
                }
        }
    }

    const int er = bm + wm * 64 + (lane >> 2);
    const int ec = bn + wn * 32 + (lane & 3) * 2;
#pragma unroll
    for (int am = 0; am < 4; am++)
#pragma unroll
        for (int bt = 0; bt < 4; bt++) {
            float* d = acc[am * 4 + bt];
            int r = er + am * 16;
            int c = ec + bt * 8;
            *(float2*)(C + (size_t)r * N + c) = make_float2(d[0], d[1]);
            *(float2*)(C + (size_t)(r + 8) * N + c) = make_float2(d[2], d[3]);
        }
}

// ---------------- RoPE + split bf16 q/k/v + q0/k0 norms (8 warps/block) ------
__global__ __launch_bounds__(256) void rope_split(const float* __restrict__ qkv,
                                                  const float* __restrict__ hyp)
{
    int bi = blockIdx.x * 8 + (threadIdx.x >> 5);   // (b*T + t)*H + h
    int h = bi % H_;
    int t = (bi / H_) % T_;
    int b = bi / (H_ * T_);
    int j = threadIdx.x & 31;

    const float* src = qkv + (size_t)(b * T_ + t) * (3 * C_) + h * HD;
    float kc = hyp[h];

    float inv = powf(10000.0f, -(float)(2 * j) / 64.0f);
    float fr = (float)t * inv;
    float cs = cosf(fr);
    float sn = sinf(fr);

    size_t dst = ((size_t)(b * H_ + h) * T_ + t) * HD;

    float q1 = src[j], q2 = src[j + 32];
    float qo1 = q1 * cs + q2 * sn;
    float qo2 = -q1 * sn + q2 * cs;
    float k1 = src[C_ + j], k2 = src[C_ + j + 32];
    float ko1 = k1 * cs + k2 * sn;
    float ko2 = -k1 * sn + k2 * cs;
    float v1 = src[2 * C_ + j], v2 = src[2 * C_ + j + 32];

    __nv_bfloat16 hh;
    hh = __float2bfloat16(qo1); g_qh[dst + j] = hh;
    g_ql[dst + j] = __float2bfloat16(qo1 - __bfloat162float(hh));
    hh = __float2bfloat16(qo2); g_qh[dst + j + 32] = hh;
    g_ql[dst + j + 32] = __float2bfloat16(qo2 - __bfloat162float(hh));
    hh = __float2bfloat16(ko1); g_kh[dst + j] = hh;
    g_kl[dst + j] = __float2bfloat16(ko1 - __bfloat162float(hh));
    hh = __float2bfloat16(ko2); g_kh[dst + j + 32] = hh;
    g_kl[dst + j + 32] = __float2bfloat16(ko2 - __bfloat162float(hh));
    hh = __float2bfloat16(v1); g_vh[dst + j] = hh;
    g_vl[dst + j] = __float2bfloat16(v1 - __bfloat162float(hh));
    hh = __float2bfloat16(v2); g_vh[dst + j + 32] = hh;
    g_vl[dst + j + 32] = __float2bfloat16(v2 - __bfloat162float(hh));

    float sq = qo1 * qo1 + qo2 * qo2;
    float sk = ko1 * ko1 + ko2 * ko2;
#pragma unroll
    for (int off = 16; off; off >>= 1) {
        sq += __shfl_xor_sync(0xffffffffu, sq, off);
        sk += __shfl_xor_sync(0xffffffffu, sk, off);
    }
    if (j == 0) {
        size_t r = (size_t)(b * H_ + h) * T_ + t;
        g_q0[r] = sqrtf(kc + sq);
        g_k0[r] = sqrtf(kc + sk);
    }
}

// ---------------- per-score hyperbolic transform (4 MUFU) ---------------------
__device__ __forceinline__ float score_p(float s, float q0, float k0,
                                         float invk, float c1) {
    float inner = s - q0 * k0;
    float arg = fmaxf(-inner * invk, 1.000001f);
    float t = fmaf(arg, arg, -1.0f);
    float sq; asm("sqrt.approx.f32 %0, %1;" : "=f"(sq) : "f"(t));
    float y = arg + sq;
    float lg; asm("lg2.approx.f32 %0, %1;" : "=f"(lg) : "f"(y));
    float u = fmaf(c1, lg, 1e-6f);
    float w; asm("rcp.approx.f32 %0, %1;" : "=f"(w) : "f"(u));
    w = fminf(w, 60.0f);
    float p; asm("ex2.approx.f32 %0, %1;" : "=f"(p) : "f"(w * 1.44269504f));
    return p;
}

// ---------------- tensorized attention, 2 regions (Q region reused as KV) -----
// region0 = [0, 36864): Q staging, then KV stages for odd st
// region1 = [36864, 73728): KV stages for even st
// k0: 2 x 256 B at 73728
#define AROWB 144
#define REG0 0
#define REG1 36864
#define SK0A 73728
#define ATT_SMEM 74240       // x2 = 148480 <= 227KB -> 2 CTAs/SM

__global__ __launch_bounds__(256, 2) void attn_mma(const float* __restrict__ hyp)
{
    extern __shared__ __align__(128) char smem[];
    const uint32_t sb = smem_u32(smem);
    const int tid = threadIdx.x;
    const int lane = tid & 31, warp = tid >> 5;
    const int qt = (int)gridDim.x - 1 - (int)blockIdx.x;
    const int h = blockIdx.y, b = blockIdx.z;
    const size_t bh = (size_t)b * H_ + h;
    const size_t qbase = (bh * T_ + (size_t)qt * 128) * HD;
    const size_t kvbase = bh * T_ * HD;
    const float* k0g = g_k0 + bh * T_;

    const float kc   = hyp[h];
    const float invk = 1.0f / kc;
    const float c1   = sqrtf(kc) * 0.69314718056f;

    const int ar0 = tid >> 3, ac0 = tid & 7;          // rows 0..31
    const int ar1 = (tid + 256) >> 3;                 // rows 32..63

    // ---- Q into region0 (hi at +0, lo at +18432)
#pragma unroll
    for (int i = 0; i < 4; i++) {
        int ch = tid + i * 256;
        int row = ch >> 3, cc = ch & 7;
        uint32_t d = sb + REG0 + row * AROWB + cc * 16;
        CP_ASYNC16(d, g_qh + qbase + row * 64 + cc * 8);
        CP_ASYNC16(d + 18432, g_ql + qbase + row * 64 + cc * 8);
    }
    CP_COMMIT();

    // KV stage layout within a region: kh +0, kl +9216, vh +18432, vl +27648
    auto issue_kv = [&](uint32_t reg, int st) {
        const uint32_t sk = sb + reg;
        const size_t tb = kvbase + (size_t)st * 64 * 64;
        uint32_t d0 = sk + ar0 * AROWB + ac0 * 16;
        const size_t s0 = tb + ar0 * 64 + ac0 * 8;
        CP_ASYNC16(d0,         g_kh + s0);
        CP_ASYNC16(d0 + 9216,  g_kl + s0);
        CP_ASYNC16(d0 + 18432, g_vh + s0);
        CP_ASYNC16(d0 + 27648, g_vl + s0);
        uint32_t d1 = sk + ar1 * AROWB + ac0 * 16;
        const size_t s1 = tb + ar1 * 64 + ac0 * 8;
        CP_ASYNC16(d1,         g_kh + s1);
        CP_ASYNC16(d1 + 9216,  g_kl + s1);
        CP_ASYNC16(d1 + 18432, g_vh + s1);
        CP_ASYNC16(d1 + 27648, g_vl + s1);
        if (tid < 16) CP_ASYNC16(sb + SK0A + (st & 1) * 256 + tid * 16,
                                 k0g + st * 64 + tid * 4);
    };

    const int ntile = 2 * qt + 2;
    issue_kv(REG1, 0);       // stage 0 -> region1
    CP_COMMIT();

    // ---- wait for Q, extract fragments
    CP_WAIT(1);
    __syncthreads();
    uint32_t qa_h[4][4], qa_l[4][4];
    const uint32_t qoff = (uint32_t)((warp * 16 + (lane & 15)) * AROWB + (lane >> 4) * 16);
#pragma unroll
    for (int g = 0; g < 4; g++) {
        ldm_x4(qa_h[g][0], qa_h[g][1], qa_h[g][2], qa_h[g][3], sb + REG0 + qoff + g * 32);
        ldm_x4(qa_l[g][0], qa_l[g][1], qa_l[g][2], qa_l[g][3], sb + REG0 + 18432 + qoff + g * 32);
    }

    const int r_in  = lane >> 2;
    const int cpair = (lane & 3) * 2;
    const int qr0 = qt * 128 + warp * 16 + r_in;
    const int qr1 = qr0 + 8;
    const float q00 = g_q0[bh * T_ + qr0];
    const float q01 = g_q0[bh * T_ + qr1];

    float O[8][4] = {};
    float ls0 = 0.0f, ls1 = 0.0f;

    for (int st = 0; st < ntile; st++) {
        __syncthreads();     // Q frags extracted (st=0) / prev compute done
        if (st + 1 < ntile) {
            issue_kv((st & 1) ? REG1 : REG0, st + 1);   // st+1 region: opposite of st
            CP_COMMIT();
        }
        if (st + 1 < ntile) { CP_WAIT(1); } else { CP_WAIT(0); }
        __syncthreads();

        const uint32_t reg = (st & 1) ? REG0 : REG1;
        const uint32_t sKh = sb + reg;
        const uint32_t sKl = sKh + 9216;
        const uint32_t sVh = sKh + 18432;
        const uint32_t sVl = sKh + 27648;
        const uint32_t k0off = SK0A + (st & 1) * 256;

        const bool maskT = (st >= 2 * qt);
        const int key_base = st * 64;

        uint32_t pa_h[4][4], pa_l[4][4];

#pragma unroll
        for (int nt = 0; nt < 8; nt++) {
            float sacc[4] = {};
            const uint32_t kb = (uint32_t)((nt * 8 + (lane & 7)) * AROWB +
                                           ((lane >> 3) & 1) * 16);
#pragma unroll
            for (int g = 0; g < 4; g++) {
                uint32_t kh[2], kl[2];
                ldm_x2(kh[0], kh[1], sKh + kb + g * 32);
                ldm_x2(kl[0], kl[1], sKl + kb + g * 32);
                mma16816(sacc, qa_h[g], kh);
                mma16816(sacc, qa_h[g], kl);
                mma16816(sacc, qa_l[g], kh);
            }

            float2 k0p = *(const float2*)(smem + k0off + (nt * 8 + cpair) * 4);
            const int keyc = key_base + nt * 8 + cpair;

            float p0 = score_p(sacc[0], q00, k0p.x, invk, c1);
            float p1 = score_p(sacc[1], q00, k0p.y, invk, c1);
            float p2 = score_p(sacc[2], q01, k0p.x, invk, c1);
            float p3 = score_p(sacc[3], q01, k0p.y, invk, c1);
            if (maskT) {
                if (keyc     > qr0) p0 = 0.0f;
                if (keyc + 1 > qr0) p1 = 0.0f;
                if (keyc     > qr1) p2 = 0.0f;
                if (keyc + 1 > qr1) p3 = 0.0f;
            }
            ls0 += p0 + p1;
            ls1 += p2 + p3;

            const int g = nt >> 1;
            const int rb = (nt & 1) * 2;
            split2(p0, p1, pa_h[g][rb + 0], pa_l[g][rb + 0]);
            split2(p2, p3, pa_h[g][rb + 1], pa_l[g][rb + 1]);
        }

#pragma unroll
        for (int dt = 0; dt < 8; dt++) {
#pragma unroll
            for (int g = 0; g < 4; g++) {
                const uint32_t vo = (uint32_t)((g * 16 + (lane & 15)) * AROWB + dt * 16);
                uint32_t vh[2], vl[2];
                ldm_x2t(vh[0], vh[1], sVh + vo);
                ldm_x2t(vl[0], vl[1], sVl + vo);
                mma16816(O[dt], pa_h[g], vh);
                mma16816(O[dt], pa_h[g], vl);
                mma16816(O[dt], pa_l[g], vh);
            }
        }
    }

    // ---- normalize and store split bf16
    ls0 += __shfl_xor_sync(0xffffffffu, ls0, 1);
    ls0 += __shfl_xor_sync(0xffffffffu, ls0, 2);
    ls1 += __shfl_xor_sync(0xffffffffu, ls1, 1);
    ls1 += __shfl_xor_sync(0xffffffffu, ls1, 2);
    const float n0 = 1.0f / ls0;
    const float n1 = 1.0f / ls1;

    const size_t o0 = ((size_t)b * T_ + qr0) * C_ + h * 64;
    const size_t o1 = ((size_t)b * T_ + qr1) * C_ + h * 64;
#pragma unroll
    for (int dt = 0; dt < 8; dt++) {
        const int c = dt * 8 + cpair;
        uint32_t hh, ll;
        split2(O[dt][0] * n0, O[dt][1] * n0, hh, ll);
        *(uint32_t*)(g_oh + o0 + c) = hh;
        *(uint32_t*)(g_ol + o0 + c) = ll;
        split2(O[dt][2] * n1, O[dt][3] * n1, hh, ll);
        *(uint32_t*)(g_oh + o1 + c) = hh;
        *(uint32_t*)(g_ol + o1 + c) = ll;
    }
}

// ---------------- launch ------------------------------------------------------
extern "C" void kernel_launch(void* const* d_in, const int* in_sizes, int n_in,
                              void* d_out, int out_size)
{
    const float* x    = (const float*)d_in[0];
    const float* Wqkv = (const float*)d_in[1];
    const float* Wout = (const float*)d_in[2];
    const float* hyp  = (const float*)d_in[3];
    float* out = (float*)d_out;

    static float* p_qkv = nullptr;
    static __nv_bfloat16 *p_xh, *p_xl, *p_w1h, *p_w1l, *p_w2h, *p_w2l, *p_oh, *p_ol;
    if (!p_qkv) {
        cudaGetSymbolAddress((void**)&p_qkv, g_qkv);
        cudaGetSymbolAddress((void**)&p_xh, g_xh);
        cudaGetSymbolAddress((void**)&p_xl, g_xl);
        cudaGetSymbolAddress((void**)&p_w1h, g_w1h);
        cudaGetSymbolAddress((void**)&p_w1l, g_w1l);
        cudaGetSymbolAddress((void**)&p_w2h, g_w2h);
        cudaGetSymbolAddress((void**)&p_w2l, g_w2l);
        cudaGetSymbolAddress((void**)&p_oh, g_oh);
        cudaGetSymbolAddress((void**)&p_ol, g_ol);
        cudaFuncSetAttribute(gemm_bf,
                             cudaFuncAttributeMaxDynamicSharedMemorySize, GSM);
        cudaFuncSetAttribute(attn_mma,
                             cudaFuncAttributeMaxDynamicSharedMemorySize, ATT_SMEM);
    }

    // 0) split conversions
    cvt_split<<<(4096 * 1024 / 4 + 255) / 256, 256>>>(x, p_xh, p_xl, 4096 * 1024 / 4);
    cvt_split<<<(3072 * 1024 / 4 + 255) / 256, 256>>>(Wqkv, p_w1h, p_w1l, 3072 * 1024 / 4);
    cvt_split<<<(1024 * 1024 / 4 + 255) / 256, 256>>>(Wout, p_w2h, p_w2l, 1024 * 1024 / 4);

    // 1) qkv = x @ W_qkv^T
    gemm_bf<<<dim3(3072 / 128, 4096 / 128), 256, GSM>>>(
        p_xh, p_xl, p_w1h, p_w1l, p_qkv, 4096, 3072, 1024);

    // 2) RoPE + split + norms
    rope_split<<<B_ * T_ * H_ / 8, 256>>>(p_qkv, hyp);

    // 3) tensorized attention
    attn_mma<<<dim3(T_ / 128, H_, B_), 256, ATT_SMEM>>>(hyp);

    // 4) out = o @ W_out^T
    gemm_bf<<<dim3(1024 / 128, 4096 / 128), 256, GSM>>>(
        p_oh, p_ol, p_w2h, p_w2l, out, 4096, 1024, 1024);
}

// round 10
// speedup vs baseline: 6.2294x; 1.0057x over previous
#include <cuda_runtime.h>
#include <cuda_bf16.h>
#include <math.h>
#include <stdint.h>

#define B_ 4
#define T_ 1024
#define C_ 1024
#define H_ 16
#define HD 64

// ---------------- scratch (static device globals; no allocation) -------------
__device__ __align__(16) float g_qkv[(size_t)4096 * 3072];
__device__ float g_q0[(size_t)B_ * H_ * T_];
__device__ float g_k0[(size_t)B_ * H_ * T_];
__device__ __align__(16) __nv_bfloat16 g_xh[(size_t)4096 * 1024];
__device__ __align__(16) __nv_bfloat16 g_xl[(size_t)4096 * 1024];
__device__ __align__(16) __nv_bfloat16 g_w1h[(size_t)3072 * 1024];
__device__ __align__(16) __nv_bfloat16 g_w1l[(size_t)3072 * 1024];
__device__ __align__(16) __nv_bfloat16 g_w2h[(size_t)1024 * 1024];
__device__ __align__(16) __nv_bfloat16 g_w2l[(size_t)1024 * 1024];
__device__ __align__(16) __nv_bfloat16 g_qh[(size_t)4096 * 1024];
__device__ __align__(16) __nv_bfloat16 g_ql[(size_t)4096 * 1024];
__device__ __align__(16) __nv_bfloat16 g_kh[(size_t)4096 * 1024];
__device__ __align__(16) __nv_bfloat16 g_kl[(size_t)4096 * 1024];
__device__ __align__(16) __nv_bfloat16 g_vh[(size_t)4096 * 1024];
__device__ __align__(16) __nv_bfloat16 g_vl[(size_t)4096 * 1024];
__device__ __align__(16) __nv_bfloat16 g_oh[(size_t)4096 * 1024];
__device__ __align__(16) __nv_bfloat16 g_ol[(size_t)4096 * 1024];

// ---------------- helpers ------------------------------------------------------
__device__ __forceinline__ uint32_t smem_u32(const void* p) {
    uint32_t a;
    asm("{ .reg .u64 t; cvta.to.shared.u64 t, %1; cvt.u32.u64 %0, t; }" : "=r"(a) : "l"(p));
    return a;
}
#define CP_ASYNC16(d, s)  asm volatile("cp.async.cg.shared.global [%0], [%1], 16;" :: "r"(d), "l"(s))
#define CP_COMMIT()       asm volatile("cp.async.commit_group;" ::: "memory")
#define CP_WAIT(n)        asm volatile("cp.async.wait_group %0;" :: "n"(n) : "memory")

__device__ __forceinline__ void ldm_x4(uint32_t& r0, uint32_t& r1, uint32_t& r2, uint32_t& r3,
                                       uint32_t addr) {
    asm volatile("ldmatrix.sync.aligned.m8n8.x4.shared.b16 {%0,%1,%2,%3}, [%4];"
                 : "=r"(r0), "=r"(r1), "=r"(r2), "=r"(r3) : "r"(addr));
}
__device__ __forceinline__ void ldm_x2(uint32_t& r0, uint32_t& r1, uint32_t addr) {
    asm volatile("ldmatrix.sync.aligned.m8n8.x2.shared.b16 {%0,%1}, [%2];"
                 : "=r"(r0), "=r"(r1) : "r"(addr));
}
__device__ __forceinline__ void ldm_x2t(uint32_t& r0, uint32_t& r1, uint32_t addr) {
    asm volatile("ldmatrix.sync.aligned.m8n8.x2.trans.shared.b16 {%0,%1}, [%2];"
                 : "=r"(r0), "=r"(r1) : "r"(addr));
}
__device__ __forceinline__ void mma16816(float* d, const uint32_t* a, const uint32_t* b) {
    asm volatile("mma.sync.aligned.m16n8k16.row.col.f32.bf16.bf16.f32 "
                 "{%0,%1,%2,%3}, {%4,%5,%6,%7}, {%8,%9}, {%0,%1,%2,%3};"
                 : "+f"(d[0]), "+f"(d[1]), "+f"(d[2]), "+f"(d[3])
                 : "r"(a[0]), "r"(a[1]), "r"(a[2]), "r"(a[3]), "r"(b[0]), "r"(b[1]));
}
__device__ __forceinline__ void split2(float x, float y, uint32_t& hi, uint32_t& lo) {
    __nv_bfloat16 hx = __float2bfloat16(x), hy = __float2bfloat16(y);
    __nv_bfloat162 h(hx, hy);
    __nv_bfloat162 l(__float2bfloat16(x - __bfloat162float(hx)),
                     __float2bfloat16(y - __bfloat162float(hy)));
    hi = *(uint32_t*)&h;
    lo = *(uint32_t*)&l;
}

// ---------------- fp32 -> bf16 hi/lo split (grid-stride) ----------------------
__global__ void cvt_split(const float* __restrict__ src,
                          __nv_bfloat16* __restrict__ hi,
                          __nv_bfloat16* __restrict__ lo, int n4)
{
    int i = blockIdx.x * blockDim.x + threadIdx.x;
    if (i >= n4) return;
    float4 v = ((const float4*)src)[i];
    uint32_t h0, l0, h1, l1;
    split2(v.x, v.y, h0, l0);
    split2(v.z, v.w, h1, l1);
    *(uint2*)(hi + (size_t)i * 4) = make_uint2(h0, h1);
    *(uint2*)(lo + (size_t)i * 4) = make_uint2(l0, l1);
}

// ---------------- GEMM: C[m][n]=sum_k A[m][k]*B[n][k], split bf16 inputs ------
// CTA tile 128(M) x 256(N) x 32(K); 8 warps, warp tile 64x64; 2-stage cp.async.
// Stage layout: Ah 0 (10240), Al 10240, Bh 20480 (20480), Bl 40960 -> 61440 B.
#define ROWB 80
#define GSTAGE 61440
#define GSM (2 * GSTAGE)     // 122880

__global__ __launch_bounds__(256, 1) void gemm_bf(
    const __nv_bfloat16* __restrict__ Ah, const __nv_bfloat16* __restrict__ Al,
    const __nv_bfloat16* __restrict__ Bh, const __nv_bfloat16* __restrict__ Bl,
    float* __restrict__ C, int M, int N, int K)
{
    extern __shared__ __align__(128) char smem[];
    const uint32_t sb = smem_u32(smem);
    const int tid = threadIdx.x;
    const int lane = tid & 31, warp = tid >> 5;
    const int wm = warp >> 2, wn = warp & 3;         // warp tile 64(M) x 64(N)
    const int bm = blockIdx.y * 128, bn = blockIdx.x * 256;
    const int NC = K / 32;

    const int ar = tid >> 2, ac = tid & 3;           // A chunk rows 0..63 (+64)

    auto issue_stage = [&](int slot, int k0) {
        const uint32_t st = sb + slot * GSTAGE;
        // A: 128 rows x 4 chunks; threads cover chunk tid and tid+256
        {
            uint32_t d = st + ar * ROWB + ac * 16;
            const size_t s0 = (size_t)(bm + ar) * K + k0 + ac * 8;
            CP_ASYNC16(d,         Ah + s0);
            CP_ASYNC16(d + 10240, Al + s0);
            uint32_t d2 = st + (ar + 64) * ROWB + ac * 16;
            const size_t s2 = (size_t)(bm + ar + 64) * K + k0 + ac * 8;
            CP_ASYNC16(d2,         Ah + s2);
            CP_ASYNC16(d2 + 10240, Al + s2);
        }
        // B: 256 rows x 4 chunks = 1024 chunks; 4 per thread
#pragma unroll
        for (int i = 0; i < 4; i++) {
            int c = tid + i * 256;
            int br = c >> 2, bc = c & 3;
            uint32_t d = st + 20480 + br * ROWB + bc * 16;
            const size_t s0 = (size_t)(bn + br) * K + k0 + bc * 8;
            CP_ASYNC16(d,         Bh + s0);
            CP_ASYNC16(d + 20480, Bl + s0);
        }
    };

    issue_stage(0, 0);
    CP_COMMIT();

    float acc[32][4] = {};

    const uint32_t aoff = (uint32_t)((wm * 64 + (lane & 15)) * ROWB + (lane >> 4) * 16);
    const uint32_t boff = (uint32_t)(20480 + (wn * 64 + (lane & 7)) * ROWB +
                                     ((lane >> 3) & 1) * 16);

    for (int i = 0; i < NC; i++) {
        if (i > 0) __syncthreads();
        if (i + 1 < NC) { issue_stage((i + 1) & 1, (i + 1) * 32); CP_COMMIT(); CP_WAIT(1); }
        else           { CP_WAIT(0); }
        __syncthreads();

        const uint32_t st = sb + (i & 1) * GSTAGE;

#pragma unroll
        for (int kk = 0; kk < 2; kk++) {
            uint32_t ah[4][4], al[4][4];
#pragma unroll
            for (int am = 0; am < 4; am++) {
                uint32_t ad = st + aoff + am * 16 * ROWB + kk * 32;
                ldm_x4(ah[am][0], ah[am][1], ah[am][2], ah[am][3], ad);
                ldm_x4(al[am][0], al[am][1], al[am][2], al[am][3], ad + 10240);
            }
#pragma unroll
            for (int nt = 0; nt < 8; nt++) {
                uint32_t bh[2], bl[2];
                uint32_t bd = st + boff + nt * 8 * ROWB + kk * 32;
                ldm_x2(bh[0], bh[1], bd);
                ldm_x2(bl[0], bl[1], bd + 20480);
#pragma unroll
                for (int am = 0; am < 4; am++) {
                    mma16816(acc[am * 8 + nt], ah[am], bh);
                    mma16816(acc[am * 8 + nt], ah[am], bl);
                    mma16816(acc[am * 8 + nt], al[am], bh);
                }
            }
        }
    }

    const int er = bm + wm * 64 + (lane >> 2);
    const int ec = bn + wn * 64 + (lane & 3) * 2;
#pragma unroll
    for (int am = 0; am < 4; am++)
#pragma unroll
        for (int nt = 0; nt < 8; nt++) {
            float* d = acc[am * 8 + nt];
            int r = er + am * 16;
            int c = ec + nt * 8;
            *(float2*)(C + (size_t)r * N + c) = make_float2(d[0], d[1]);
            *(float2*)(C + (size_t)(r + 8) * N + c) = make_float2(d[2], d[3]);
        }
}

// ---------------- RoPE + split bf16 q/k/v + q0/k0 norms (8 warps/block) ------
__global__ __launch_bounds__(256) void rope_split(const float* __restrict__ qkv,
                                                  const float* __restrict__ hyp)
{
    int bi = blockIdx.x * 8 + (threadIdx.x >> 5);
    int h = bi % H_;
    int t = (bi / H_) % T_;
    int b = bi / (H_ * T_);
    int j = threadIdx.x & 31;

    const float* src = qkv + (size_t)(b * T_ + t) * (3 * C_) + h * HD;
    float kc = hyp[h];

    float inv = powf(10000.0f, -(float)(2 * j) / 64.0f);
    float fr = (float)t * inv;
    float cs = cosf(fr);
    float sn = sinf(fr);

    size_t dst = ((size_t)(b * H_ + h) * T_ + t) * HD;

    float q1 = src[j], q2 = src[j + 32];
    float qo1 = q1 * cs + q2 * sn;
    float qo2 = -q1 * sn + q2 * cs;
    float k1 = src[C_ + j], k2 = src[C_ + j + 32];
    float ko1 = k1 * cs + k2 * sn;
    float ko2 = -k1 * sn + k2 * cs;
    float v1 = src[2 * C_ + j], v2 = src[2 * C_ + j + 32];

    __nv_bfloat16 hh;
    hh = __float2bfloat16(qo1); g_qh[dst + j] = hh;
    g_ql[dst + j] = __float2bfloat16(qo1 - __bfloat162float(hh));
    hh = __float2bfloat16(qo2); g_qh[dst + j + 32] = hh;
    g_ql[dst + j + 32] = __float2bfloat16(qo2 - __bfloat162float(hh));
    hh = __float2bfloat16(ko1); g_kh[dst + j] = hh;
    g_kl[dst + j] = __float2bfloat16(ko1 - __bfloat162float(hh));
    hh = __float2bfloat16(ko2); g_kh[dst + j + 32] = hh;
    g_kl[dst + j + 32] = __float2bfloat16(ko2 - __bfloat162float(hh));
    hh = __float2bfloat16(v1); g_vh[dst + j] = hh;
    g_vl[dst + j] = __float2bfloat16(v1 - __bfloat162float(hh));
    hh = __float2bfloat16(v2); g_vh[dst + j + 32] = hh;
    g_vl[dst + j + 32] = __float2bfloat16(v2 - __bfloat162float(hh));

    float sq = qo1 * qo1 + qo2 * qo2;
    float sk = ko1 * ko1 + ko2 * ko2;
#pragma unroll
    for (int off = 16; off; off >>= 1) {
        sq += __shfl_xor_sync(0xffffffffu, sq, off);
        sk += __shfl_xor_sync(0xffffffffu, sk, off);
    }
    if (j == 0) {
        size_t r = (size_t)(b * H_ + h) * T_ + t;
        g_q0[r] = sqrtf(kc + sq);
        g_k0[r] = sqrtf(kc + sk);
    }
}

// ---------------- per-score hyperbolic transform (4 MUFU) ---------------------
__device__ __forceinline__ float score_p(float s, float q0, float k0,
                                         float invk, float c1) {
    float inner = s - q0 * k0;
    float arg = fmaxf(-inner * invk, 1.000001f);
    float t = fmaf(arg, arg, -1.0f);
    float sq; asm("sqrt.approx.f32 %0, %1;" : "=f"(sq) : "f"(t));
    float y = arg + sq;
    float lg; asm("lg2.approx.f32 %0, %1;" : "=f"(lg) : "f"(y));
    float u = fmaf(c1, lg, 1e-6f);
    float w; asm("rcp.approx.f32 %0, %1;" : "=f"(w) : "f"(u));
    w = fminf(w, 60.0f);
    float p; asm("ex2.approx.f32 %0, %1;" : "=f"(p) : "f"(w * 1.44269504f));
    return p;
}

// ---------------- tensorized attention (unchanged from R9) --------------------
#define AROWB 144
#define REG0 0
#define REG1 36864
#define SK0A 73728
#define ATT_SMEM 74240

__global__ __launch_bounds__(256, 2) void attn_mma(const float* __restrict__ hyp)
{
    extern __shared__ __align__(128) char smem[];
    const uint32_t sb = smem_u32(smem);
    const int tid = threadIdx.x;
    const int lane = tid & 31, warp = tid >> 5;
    const int qt = (int)gridDim.x - 1 - (int)blockIdx.x;
    const int h = blockIdx.y, b = blockIdx.z;
    const size_t bh = (size_t)b * H_ + h;
    const size_t qbase = (bh * T_ + (size_t)qt * 128) * HD;
    const size_t kvbase = bh * T_ * HD;
    const float* k0g = g_k0 + bh * T_;

    const float kc   = hyp[h];
    const float invk = 1.0f / kc;
    const float c1   = sqrtf(kc) * 0.69314718056f;

    const int ar0 = tid >> 3, ac0 = tid & 7;
    const int ar1 = (tid + 256) >> 3;

#pragma unroll
    for (int i = 0; i < 4; i++) {
        int ch = tid + i * 256;
        int row = ch >> 3, cc = ch & 7;
        uint32_t d = sb + REG0 + row * AROWB + cc * 16;
        CP_ASYNC16(d, g_qh + qbase + row * 64 + cc * 8);
        CP_ASYNC16(d + 18432, g_ql + qbase + row * 64 + cc * 8);
    }
    CP_COMMIT();

    auto issue_kv = [&](uint32_t reg, int st) {
        const uint32_t sk = sb + reg;
        const size_t tb = kvbase + (size_t)st * 64 * 64;
        uint32_t d0 = sk + ar0 * AROWB + ac0 * 16;
        const size_t s0 = tb + ar0 * 64 + ac0 * 8;
        CP_ASYNC16(d0,         g_kh + s0);
        CP_ASYNC16(d0 + 9216,  g_kl + s0);
        CP_ASYNC16(d0 + 18432, g_vh + s0);
        CP_ASYNC16(d0 + 27648, g_vl + s0);
        uint32_t d1 = sk + ar1 * AROWB + ac0 * 16;
        const size_t s1 = tb + ar1 * 64 + ac0 * 8;
        CP_ASYNC16(d1,         g_kh + s1);
        CP_ASYNC16(d1 + 9216,  g_kl + s1);
        CP_ASYNC16(d1 + 18432, g_vh + s1);
        CP_ASYNC16(d1 + 27648, g_vl + s1);
        if (tid < 16) CP_ASYNC16(sb + SK0A + (st & 1) * 256 + tid * 16,
                                 k0g + st * 64 + tid * 4);
    };

    const int ntile = 2 * qt + 2;
    issue_kv(REG1, 0);
    CP_COMMIT();

    CP_WAIT(1);
    __syncthreads();
    uint32_t qa_h[4][4], qa_l[4][4];
    const uint32_t qoff = (uint32_t)((warp * 16 + (lane & 15)) * AROWB + (lane >> 4) * 16);
#pragma unroll
    for (int g = 0; g < 4; g++) {
        ldm_x4(qa_h[g][0], qa_h[g][1], qa_h[g][2], qa_h[g][3], sb + REG0 + qoff + g * 32);
        ldm_x4(qa_l[g][0], qa_l[g][1], qa_l[g][2], qa_l[g][3], sb + REG0 + 18432 + qoff + g * 32);
    }

    const int r_in  = lane >> 2;
    const int cpair = (lane & 3) * 2;
    const int qr0 = qt * 128 + warp * 16 + r_in;
    const int qr1 = qr0 + 8;
    const float q00 = g_q0[bh * T_ + qr0];
    const float q01 = g_q0[bh * T_ + qr1];

    float O[8][4] = {};
    float ls0 = 0.0f, ls1 = 0.0f;

    for (int st = 0; st < ntile; st++) {
        __syncthreads();
        if (st + 1 < ntile) {
            issue_kv((st & 1) ? REG1 : REG0, st + 1);
            CP_COMMIT();
        }
        if (st + 1 < ntile) { CP_WAIT(1); } else { CP_WAIT(0); }
        __syncthreads();

        const uint32_t reg = (st & 1) ? REG0 : REG1;
        const uint32_t sKh = sb + reg;
        const uint32_t sKl = sKh + 9216;
        const uint32_t sVh = sKh + 18432;
        const uint32_t sVl = sKh + 27648;
        const uint32_t k0off = SK0A + (st & 1) * 256;

        const bool maskT = (st >= 2 * qt);
        const int key_base = st * 64;

        uint32_t pa_h[4][4], pa_l[4][4];

#pragma unroll
        for (int nt = 0; nt < 8; nt++) {
            float sacc[4] = {};
            const uint32_t kb = (uint32_t)((nt * 8 + (lane & 7)) * AROWB +
                                           ((lane >> 3) & 1) * 16);
#pragma unroll
            for (int g = 0; g < 4; g++) {
                uint32_t kh[2], kl[2];
                ldm_x2(kh[0], kh[1], sKh + kb + g * 32);
                ldm_x2(kl[0], kl[1], sKl + kb + g * 32);
                mma16816(sacc, qa_h[g], kh);
                mma16816(sacc, qa_h[g], kl);
                mma16816(sacc, qa_l[g], kh);
            }

            float2 k0p = *(const float2*)(smem + k0off + (nt * 8 + cpair) * 4);
            const int keyc = key_base + nt * 8 + cpair;

            float p0 = score_p(sacc[0], q00, k0p.x, invk, c1);
            float p1 = score_p(sacc[1], q00, k0p.y, invk, c1);
            float p2 = score_p(sacc[2], q01, k0p.x, invk, c1);
            float p3 = score_p(sacc[3], q01, k0p.y, invk, c1);
            if (maskT) {
                if (keyc     > qr0) p0 = 0.0f;
                if (keyc + 1 > qr0) p1 = 0.0f;
                if (keyc     > qr1) p2 = 0.0f;
                if (keyc + 1 > qr1) p3 = 0.0f;
            }
            ls0 += p0 + p1;
            ls1 += p2 + p3;

            const int g = nt >> 1;
            const int rb = (nt & 1) * 2;
            split2(p0, p1, pa_h[g][rb + 0], pa_l[g][rb + 0]);
            split2(p2, p3, pa_h[g][rb + 1], pa_l[g][rb + 1]);
        }

#pragma unroll
        for (int dt = 0; dt < 8; dt++) {
#pragma unroll
            for (int g = 0; g < 4; g++) {
                const uint32_t vo = (uint32_t)((g * 16 + (lane & 15)) * AROWB + dt * 16);
                uint32_t vh[2], vl[2];
                ldm_x2t(vh[0], vh[1], sVh + vo);
                ldm_x2t(vl[0], vl[1], sVl + vo);
                mma16816(O[dt], pa_h[g], vh);
                mma16816(O[dt], pa_h[g], vl);
                mma16816(O[dt], pa_l[g], vh);
            }
        }
    }

    ls0 += __shfl_xor_sync(0xffffffffu, ls0, 1);
    ls0 += __shfl_xor_sync(0xffffffffu, ls0, 2);
    ls1 += __shfl_xor_sync(0xffffffffu, ls1, 1);
    ls1 += __shfl_xor_sync(0xffffffffu, ls1, 2);
    const float n0 = 1.0f / ls0;
    const float n1 = 1.0f / ls1;

    const size_t o0 = ((size_t)b * T_ + qr0) * C_ + h * 64;
    const size_t o1 = ((size_t)b * T_ + qr1) * C_ + h * 64;
#pragma unroll
    for (int dt = 0; dt < 8; dt++) {
        const int c = dt * 8 + cpair;
        uint32_t hh, ll;
        split2(O[dt][0] * n0, O[dt][1] * n0, hh, ll);
        *(uint32_t*)(g_oh + o0 + c) = hh;
        *(uint32_t*)(g_ol + o0 + c) = ll;
        split2(O[dt][2] * n1, O[dt][3] * n1, hh, ll);
        *(uint32_t*)(g_oh + o1 + c) = hh;
        *(uint32_t*)(g_ol + o1 + c) = ll;
    }
}

// ---------------- launch ------------------------------------------------------
extern "C" void kernel_launch(void* const* d_in, const int* in_sizes, int n_in,
                              void* d_out, int out_size)
{
    const float* x    = (const float*)d_in[0];
    const float* Wqkv = (const float*)d_in[1];
    const float* Wout = (const float*)d_in[2];
    const float* hyp  = (const float*)d_in[3];
    float* out = (float*)d_out;

    static float* p_qkv = nullptr;
    static __nv_bfloat16 *p_xh, *p_xl, *p_w1h, *p_w1l, *p_w2h, *p_w2l, *p_oh, *p_ol;
    if (!p_qkv) {
        cudaGetSymbolAddress((void**)&p_qkv, g_qkv);
        cudaGetSymbolAddress((void**)&p_xh, g_xh);
        cudaGetSymbolAddress((void**)&p_xl, g_xl);
        cudaGetSymbolAddress((void**)&p_w1h, g_w1h);
        cudaGetSymbolAddress((void**)&p_w1l, g_w1l);
        cudaGetSymbolAddress((void**)&p_w2h, g_w2h);
        cudaGetSymbolAddress((void**)&p_w2l, g_w2l);
        cudaGetSymbolAddress((void**)&p_oh, g_oh);
        cudaGetSymbolAddress((void**)&p_ol, g_ol);
        cudaFuncSetAttribute(gemm_bf,
                             cudaFuncAttributeMaxDynamicSharedMemorySize, GSM);
        cudaFuncSetAttribute(attn_mma,
                             cudaFuncAttributeMaxDynamicSharedMemorySize, ATT_SMEM);
    }

    // 0) split conversions
    cvt_split<<<(4096 * 1024 / 4 + 255) / 256, 256>>>(x, p_xh, p_xl, 4096 * 1024 / 4);
    cvt_split<<<(3072 * 1024 / 4 + 255) / 256, 256>>>(Wqkv, p_w1h, p_w1l, 3072 * 1024 / 4);
    cvt_split<<<(1024 * 1024 / 4 + 255) / 256, 256>>>(Wout, p_w2h, p_w2l, 1024 * 1024 / 4);

    // 1) qkv = x @ W_qkv^T  (CTA tile 128x256)
    gemm_bf<<<dim3(3072 / 256, 4096 / 128), 256, GSM>>>(
        p_xh, p_xl, p_w1h, p_w1l, p_qkv, 4096, 3072, 1024);

    // 2) RoPE + split + norms
    rope_split<<<B_ * T_ * H_ / 8, 256>>>(p_qkv, hyp);

    // 3) tensorized attention
    attn_mma<<<dim3(T_ / 128, H_, B_), 256, ATT_SMEM>>>(hyp);

    // 4) out = o @ W_out^T
    gemm_bf<<<dim3(1024 / 256, 4096 / 128), 256, GSM>>>(
        p_oh, p_ol, p_w2h, p_w2l, out, 4096, 1024, 1024);
}